// round 1
// baseline (speedup 1.0000x reference)
#include <cuda_runtime.h>
#include <cuda_bf16.h>
#include <math.h>

// Problem dims
#define BB 64
#define TT 24
#define NN 512
#define CC 2
#define HH 64
#define DD 16
#define II 66      // C + H
#define KI 132     // K * II
#define IP 72      // padded input width for GEMM

// ---------------- device scratch (static globals; no allocation) ----------------
__device__ float d_A[NN * NN];                    // adjacency, 1 MB
__device__ float d_Wnzr[NN * KI * 128];           // node weights zr, 34.6 MB
__device__ float d_bnzr[NN * 128];
__device__ float d_Wnc[NN * KI * 64];             // node weights cand, 17.3 MB
__device__ float d_bnc[NN * 64];
__device__ float d_u[BB * NN * IP];               // u1 = [xt, h, pad]
__device__ float d_u2[BB * NN * IP];              // u2 = [xt, r*h, pad]
__device__ float d_g[BB * NN * IP];               // A @ u
__device__ float d_h[BB * NN * HH];               // hidden state
__device__ float d_z[BB * NN * HH];               // update gate

// ---------------- A = softmax(relu(E1 E1^T)) row-wise ----------------
__global__ void compute_A_kernel(const float* __restrict__ E1) {
    int n = blockIdx.x;
    __shared__ float en[DD];
    __shared__ float red[256];
    int tid = threadIdx.x;  // 256
    if (tid < DD) en[tid] = E1[n * DD + tid];
    __syncthreads();

    float v[2];
#pragma unroll
    for (int j = 0; j < 2; j++) {
        int m = tid + j * 256;
        const float* em = E1 + m * DD;
        float s = 0.f;
#pragma unroll
        for (int d = 0; d < DD; d++) s = fmaf(en[d], em[d], s);
        v[j] = fmaxf(s, 0.f);
    }
    // block max
    red[tid] = fmaxf(v[0], v[1]);
    __syncthreads();
    for (int s = 128; s > 0; s >>= 1) {
        if (tid < s) red[tid] = fmaxf(red[tid], red[tid + s]);
        __syncthreads();
    }
    float mx = red[0];
    __syncthreads();
    float e0 = expf(v[0] - mx), e1 = expf(v[1] - mx);
    red[tid] = e0 + e1;
    __syncthreads();
    for (int s = 128; s > 0; s >>= 1) {
        if (tid < s) red[tid] += red[tid + s];
        __syncthreads();
    }
    float inv = 1.f / red[0];
    d_A[n * NN + tid] = e0 * inv;
    d_A[n * NN + tid + 256] = e1 * inv;
}

// ---------------- node-adaptive weight materialization ----------------
// out[n*rowlen + rem] = sum_d E1[n,d] * pool[d*rowlen + rem]
__global__ void mix_pool_kernel(const float* __restrict__ pool,
                                const float* __restrict__ E1,
                                int which, int rowlen, int total) {
    int idx = blockIdx.x * blockDim.x + threadIdx.x;
    if (idx >= total) return;
    float* out = (which == 0) ? d_Wnzr : (which == 1) ? d_Wnc
               : (which == 2) ? d_bnzr : d_bnc;
    int n = idx / rowlen;
    int rem = idx - n * rowlen;
    float s = 0.f;
#pragma unroll
    for (int d = 0; d < DD; d++)
        s = fmaf(E1[n * DD + d], pool[d * rowlen + rem], s);
    out[idx] = s;
}

// ---------------- init: h = 0, u1 = [x_0, 0, pad0] ----------------
__global__ void init_kernel(const float* __restrict__ x) {
    int idx = blockIdx.x * blockDim.x + threadIdx.x;
    if (idx >= BB * NN * IP) return;
    int b = idx / (NN * IP);
    int r = idx - b * (NN * IP);
    int n = r / IP;
    int ip = r - n * IP;
    float v = 0.f;
    if (ip < CC) v = x[((b * TT + 0) * NN + n) * CC + ip];
    d_u[idx] = v;
    if (idx < BB * NN * HH) d_h[idx] = 0.f;
}

// ---------------- g[b] = A (512x512) @ u[b] (512x72) ----------------
// grid (8, 64), 288 threads; BM=64, BN=72, BK=16, thread tile 4x4
__global__ void gemm_Au_kernel(int use_u2) {
    __shared__ float4 As4[16][16];  // [kk][m4], m = m4*4
    __shared__ float4 Us4[16][18];  // [kk][c4], c = c4*4
    const float* u = use_u2 ? d_u2 : d_u;

    int b = blockIdx.y;
    int row0 = blockIdx.x * 64;
    int tid = threadIdx.x;           // 0..287
    int ty = tid / 18;               // 0..15 row group (4 rows)
    int tx = tid - ty * 18;          // 0..17 col group (4 cols)
    const float* ub = u + b * NN * IP;
    float* As = (float*)As4;         // [kk][64]

    float acc[4][4];
#pragma unroll
    for (int i = 0; i < 4; i++)
#pragma unroll
        for (int j = 0; j < 4; j++) acc[i][j] = 0.f;

    for (int k0 = 0; k0 < NN; k0 += 16) {
        // A tile: 64 rows x 16 k -> As[k][m]
        for (int i = tid; i < 1024; i += 288) {
            int r = i >> 4, kc = i & 15;
            As[kc * 64 + r] = d_A[(row0 + r) * NN + k0 + kc];
        }
        // U tile: 16 k x 72 c  (exactly 288 float4)
        {
            int kr = tid / 18, c4 = tid - kr * 18;
            Us4[kr][c4] = *(const float4*)(ub + (k0 + kr) * IP + c4 * 4);
        }
        __syncthreads();
#pragma unroll
        for (int kk = 0; kk < 16; kk++) {
            float4 a = As4[kk][ty];
            float4 uu = Us4[kk][tx];
            acc[0][0] = fmaf(a.x, uu.x, acc[0][0]);
            acc[0][1] = fmaf(a.x, uu.y, acc[0][1]);
            acc[0][2] = fmaf(a.x, uu.z, acc[0][2]);
            acc[0][3] = fmaf(a.x, uu.w, acc[0][3]);
            acc[1][0] = fmaf(a.y, uu.x, acc[1][0]);
            acc[1][1] = fmaf(a.y, uu.y, acc[1][1]);
            acc[1][2] = fmaf(a.y, uu.z, acc[1][2]);
            acc[1][3] = fmaf(a.y, uu.w, acc[1][3]);
            acc[2][0] = fmaf(a.z, uu.x, acc[2][0]);
            acc[2][1] = fmaf(a.z, uu.y, acc[2][1]);
            acc[2][2] = fmaf(a.z, uu.z, acc[2][2]);
            acc[2][3] = fmaf(a.z, uu.w, acc[2][3]);
            acc[3][0] = fmaf(a.w, uu.x, acc[3][0]);
            acc[3][1] = fmaf(a.w, uu.y, acc[3][1]);
            acc[3][2] = fmaf(a.w, uu.z, acc[3][2]);
            acc[3][3] = fmaf(a.w, uu.w, acc[3][3]);
        }
        __syncthreads();
    }
    float* gb = d_g + b * NN * IP;
#pragma unroll
    for (int i = 0; i < 4; i++) {
        float4 o;
        o.x = acc[i][0]; o.y = acc[i][1]; o.z = acc[i][2]; o.w = acc[i][3];
        *(float4*)(gb + (row0 + ty * 4 + i) * IP + tx * 4) = o;
    }
}

// ---------------- zr gate: per-node GEMM (64b x 128o, K=132) ----------------
// block = node n, 512 threads: bg = tid&15 (b = bg + 16*j), og = tid>>4 (o = og*4+c)
__global__ void gate_zr_kernel() {
    int n = blockIdx.x;
    __shared__ float sin_[64][133];  // [b][ki], stride 133 (odd) conflict-free
    int tid = threadIdx.x;  // 512

    for (int idx = tid; idx < 64 * 66; idx += 512) {
        int b = idx / 66, i = idx - b * 66;
        int row = (b * NN + n) * IP;
        sin_[b][i] = d_u[row + i];
        sin_[b][66 + i] = d_g[row + i];
    }
    __syncthreads();

    int bg = tid & 15;
    int og = tid >> 4;  // 0..31
    float4 bias = *((const float4*)(d_bnzr + n * 128) + og);
    float acc[4][4];
#pragma unroll
    for (int j = 0; j < 4; j++) {
        acc[j][0] = bias.x; acc[j][1] = bias.y; acc[j][2] = bias.z; acc[j][3] = bias.w;
    }
    const float4* wp = (const float4*)(d_Wnzr + (size_t)n * KI * 128) + og;
#pragma unroll 4
    for (int ki = 0; ki < KI; ki++) {
        float4 w = wp[ki * 32];
#pragma unroll
        for (int j = 0; j < 4; j++) {
            float uv = sin_[bg + 16 * j][ki];
            acc[j][0] = fmaf(uv, w.x, acc[j][0]);
            acc[j][1] = fmaf(uv, w.y, acc[j][1]);
            acc[j][2] = fmaf(uv, w.z, acc[j][2]);
            acc[j][3] = fmaf(uv, w.w, acc[j][3]);
        }
    }
#pragma unroll
    for (int j = 0; j < 4; j++) {
        int b = bg + 16 * j;
        int row = b * NN + n;
#pragma unroll
        for (int c = 0; c < 4; c++) {
            int o = og * 4 + c;
            float s = 1.f / (1.f + expf(-acc[j][c]));
            if (o < HH) {
                d_z[row * HH + o] = s;
            } else {
                int oo = o - HH;
                d_u2[row * IP + CC + oo] = s * d_h[row * HH + oo];
            }
        }
    }
    // u2 cols 0..1 (copy xt from u1) and zero padding
    if (og == 0) {
#pragma unroll
        for (int j = 0; j < 4; j++) {
            int row = (bg + 16 * j) * NN + n;
            d_u2[row * IP + 0] = d_u[row * IP + 0];
            d_u2[row * IP + 1] = d_u[row * IP + 1];
#pragma unroll
            for (int p = 66; p < IP; p++) d_u2[row * IP + p] = 0.f;
        }
    }
}

// ---------------- candidate gate + state update + next-step u1 ----------------
// block = node n, 256 threads: bg = tid&15, og = tid>>4 (0..15), o = og*4+c
__global__ void gate_c_kernel(const float* __restrict__ x, int t) {
    int n = blockIdx.x;
    __shared__ float sin_[64][133];
    int tid = threadIdx.x;  // 256

    for (int idx = tid; idx < 64 * 66; idx += 256) {
        int b = idx / 66, i = idx - b * 66;
        int row = (b * NN + n) * IP;
        sin_[b][i] = d_u2[row + i];
        sin_[b][66 + i] = d_g[row + i];
    }
    __syncthreads();

    int bg = tid & 15;
    int og = tid >> 4;  // 0..15
    float4 bias = *((const float4*)(d_bnc + n * 64) + og);
    float acc[4][4];
#pragma unroll
    for (int j = 0; j < 4; j++) {
        acc[j][0] = bias.x; acc[j][1] = bias.y; acc[j][2] = bias.z; acc[j][3] = bias.w;
    }
    const float4* wp = (const float4*)(d_Wnc + (size_t)n * KI * 64) + og;
#pragma unroll 4
    for (int ki = 0; ki < KI; ki++) {
        float4 w = wp[ki * 16];
#pragma unroll
        for (int j = 0; j < 4; j++) {
            float uv = sin_[bg + 16 * j][ki];
            acc[j][0] = fmaf(uv, w.x, acc[j][0]);
            acc[j][1] = fmaf(uv, w.y, acc[j][1]);
            acc[j][2] = fmaf(uv, w.z, acc[j][2]);
            acc[j][3] = fmaf(uv, w.w, acc[j][3]);
        }
    }
    bool more = (t < TT - 1);
#pragma unroll
    for (int j = 0; j < 4; j++) {
        int b = bg + 16 * j;
        int row = b * NN + n;
#pragma unroll
        for (int c = 0; c < 4; c++) {
            int o = og * 4 + c;
            float hc = tanhf(acc[j][c]);
            float z = d_z[row * HH + o];
            float hn = z * d_h[row * HH + o] + (1.f - z) * hc;
            d_h[row * HH + o] = hn;
            if (more) d_u[row * IP + CC + o] = hn;
        }
    }
    if (og == 0 && more) {
#pragma unroll
        for (int j = 0; j < 4; j++) {
            int b = bg + 16 * j;
            int row = b * NN + n;
            d_u[row * IP + 0] = x[((b * TT + t + 1) * NN + n) * CC + 0];
            d_u[row * IP + 1] = x[((b * TT + t + 1) * NN + n) * CC + 1];
#pragma unroll
            for (int p = 66; p < IP; p++) d_u[row * IP + p] = 0.f;
        }
    }
}

// ---------------- readout: out[b,n] = h[b,n,:] . Wout + bout ----------------
__global__ void readout_kernel(const float* __restrict__ Wout,
                               const float* __restrict__ bout,
                               float* __restrict__ out) {
    int idx = blockIdx.x * blockDim.x + threadIdx.x;
    if (idx >= BB * NN) return;
    float s = bout[0];
    const float* hp = d_h + (size_t)idx * HH;
#pragma unroll
    for (int o = 0; o < HH; o++) s = fmaf(hp[o], Wout[o], s);
    out[idx] = s;
}

// ---------------- launch ----------------
extern "C" void kernel_launch(void* const* d_in, const int* in_sizes, int n_in,
                              void* d_out, int out_size) {
    const float* x    = (const float*)d_in[0];
    const float* E1   = (const float*)d_in[1];
    const float* Wzr  = (const float*)d_in[2];
    const float* bzr  = (const float*)d_in[3];
    const float* Wc   = (const float*)d_in[4];
    const float* bc   = (const float*)d_in[5];
    const float* Wout = (const float*)d_in[6];
    const float* bout = (const float*)d_in[7];
    float* out = (float*)d_out;

    compute_A_kernel<<<NN, 256>>>(E1);

    // node-adaptive weights
    {
        int tot0 = NN * KI * 128;  // 8,650,752
        mix_pool_kernel<<<(tot0 + 255) / 256, 256>>>(Wzr, E1, 0, KI * 128, tot0);
        int tot1 = NN * KI * 64;   // 4,325,376
        mix_pool_kernel<<<(tot1 + 255) / 256, 256>>>(Wc, E1, 1, KI * 64, tot1);
        int tot2 = NN * 128;
        mix_pool_kernel<<<(tot2 + 255) / 256, 256>>>(bzr, E1, 2, 128, tot2);
        int tot3 = NN * 64;
        mix_pool_kernel<<<(tot3 + 255) / 256, 256>>>(bc, E1, 3, 64, tot3);
    }

    init_kernel<<<(BB * NN * IP + 255) / 256, 256>>>(x);

    dim3 ggrid(NN / 64, BB);
    for (int t = 0; t < TT; t++) {
        gemm_Au_kernel<<<ggrid, 288>>>(0);
        gate_zr_kernel<<<NN, 512>>>();
        gemm_Au_kernel<<<ggrid, 288>>>(1);
        gate_c_kernel<<<NN, 256>>>(x, t);
    }

    readout_kernel<<<(BB * NN + 255) / 256, 256>>>(Wout, bout, out);
}

// round 3
// speedup vs baseline: 1.5217x; 1.5217x over previous
#include <cuda_runtime.h>
#include <cuda_bf16.h>
#include <math.h>
#include <stdint.h>

// Problem dims
#define BB 64
#define TT 24
#define NN 512
#define CC 2
#define HH 64
#define DD 16
#define II 66      // C + H
#define KI 132     // K * II
#define IP 72      // padded input width
#define NT (BB*IP) // 4608 transposed rows (b,c)

// ---------------- device scratch ----------------
__device__ float d_Wnzr[NN * KI * 128];
__device__ float d_bnzr[NN * 128];
__device__ float d_Wnc[NN * KI * 64];
__device__ float d_bnc[NN * 64];
__device__ float d_u[BB * NN * IP];
__device__ float d_u2[BB * NN * IP];
__device__ float d_g[BB * NN * IP];
__device__ float d_h[BB * NN * HH];
__device__ float d_z[BB * NN * HH];

// bf16 hi/lo split operands for tensor-core GEMM
__device__ __nv_bfloat16 d_Ah[NN * NN];
__device__ __nv_bfloat16 d_Al[NN * NN];
__device__ __nv_bfloat16 d_uTh[NT * NN];
__device__ __nv_bfloat16 d_uTl[NT * NN];

// ---------------- helpers ----------------
__device__ __forceinline__ uint32_t smem_u32(const void* p) {
    uint32_t a;
    asm("{ .reg .u64 t; cvta.to.shared.u64 t, %1; cvt.u32.u64 %0, t; }" : "=r"(a) : "l"(p));
    return a;
}
__device__ __forceinline__ void cp16(uint32_t saddr, const void* g) {
    asm volatile("cp.async.cg.shared.global [%0], [%1], 16;" :: "r"(saddr), "l"(g));
}
#define CP_COMMIT() asm volatile("cp.async.commit_group;" ::: "memory")

__device__ __forceinline__ void ldsm4(uint32_t& r0, uint32_t& r1, uint32_t& r2, uint32_t& r3,
                                      uint32_t addr) {
    asm volatile("ldmatrix.sync.aligned.m8n8.x4.shared.b16 {%0,%1,%2,%3}, [%4];"
                 : "=r"(r0), "=r"(r1), "=r"(r2), "=r"(r3) : "r"(addr));
}
__device__ __forceinline__ void mma_bf16(float* c, const uint32_t* a, uint32_t b0, uint32_t b1) {
    asm volatile(
        "mma.sync.aligned.m16n8k16.row.col.f32.bf16.bf16.f32 "
        "{%0,%1,%2,%3}, {%4,%5,%6,%7}, {%8,%9}, {%0,%1,%2,%3};"
        : "+f"(c[0]), "+f"(c[1]), "+f"(c[2]), "+f"(c[3])
        : "r"(a[0]), "r"(a[1]), "r"(a[2]), "r"(a[3]), "r"(b0), "r"(b1));
}
__device__ __forceinline__ unsigned short bf_bits(__nv_bfloat16 h) {
    return *reinterpret_cast<unsigned short*>(&h);
}

// ---------------- A = softmax(relu(E1 E1^T)), emitted as bf16 hi/lo ----------------
__global__ void compute_A_kernel(const float* __restrict__ E1) {
    int n = blockIdx.x;
    __shared__ float en[DD];
    __shared__ float red[256];
    int tid = threadIdx.x;
    if (tid < DD) en[tid] = E1[n * DD + tid];
    __syncthreads();

    float v[2];
#pragma unroll
    for (int j = 0; j < 2; j++) {
        int m = tid + j * 256;
        const float* em = E1 + m * DD;
        float s = 0.f;
#pragma unroll
        for (int d = 0; d < DD; d++) s = fmaf(en[d], em[d], s);
        v[j] = fmaxf(s, 0.f);
    }
    red[tid] = fmaxf(v[0], v[1]);
    __syncthreads();
    for (int s = 128; s > 0; s >>= 1) {
        if (tid < s) red[tid] = fmaxf(red[tid], red[tid + s]);
        __syncthreads();
    }
    float mx = red[0];
    __syncthreads();
    float e0 = expf(v[0] - mx), e1 = expf(v[1] - mx);
    red[tid] = e0 + e1;
    __syncthreads();
    for (int s = 128; s > 0; s >>= 1) {
        if (tid < s) red[tid] += red[tid + s];
        __syncthreads();
    }
    float inv = 1.f / red[0];
    float a0 = e0 * inv, a1 = e1 * inv;
    __nv_bfloat16 h0 = __float2bfloat16(a0);
    __nv_bfloat16 h1 = __float2bfloat16(a1);
    d_Ah[n * NN + tid] = h0;
    d_Ah[n * NN + tid + 256] = h1;
    d_Al[n * NN + tid] = __float2bfloat16(a0 - __bfloat162float(h0));
    d_Al[n * NN + tid + 256] = __float2bfloat16(a1 - __bfloat162float(h1));
}

// ---------------- node-adaptive weight materialization ----------------
__global__ void mix_pool_kernel(const float* __restrict__ pool,
                                const float* __restrict__ E1,
                                int which, int rowlen, int total) {
    int idx = blockIdx.x * blockDim.x + threadIdx.x;
    if (idx >= total) return;
    float* out = (which == 0) ? d_Wnzr : (which == 1) ? d_Wnc
               : (which == 2) ? d_bnzr : d_bnc;
    int n = idx / rowlen;
    int rem = idx - n * rowlen;
    float s = 0.f;
#pragma unroll
    for (int d = 0; d < DD; d++)
        s = fmaf(E1[n * DD + d], pool[d * rowlen + rem], s);
    out[idx] = s;
}

// ---------------- init ----------------
__global__ void init_kernel(const float* __restrict__ x) {
    int idx = blockIdx.x * blockDim.x + threadIdx.x;
    if (idx >= BB * NN * IP) return;
    int b = idx / (NN * IP);
    int r = idx - b * (NN * IP);
    int n = r / IP;
    int ip = r - n * IP;
    float v = 0.f;
    if (ip < CC) v = x[((b * TT + 0) * NN + n) * CC + ip];
    d_u[idx] = v;
    if (idx < BB * NN * HH) d_h[idx] = 0.f;
}

// ---------------- transpose + bf16 hi/lo decompose: u[b][n][c] -> uT[(b,c)][n] ----------------
__global__ void transpose_kernel(int use_u2) {
    const float* src = use_u2 ? d_u2 : d_u;
    __shared__ float s[IP][129];
    int b = blockIdx.y, n0 = blockIdx.x * 128;
    const float* up = src + (size_t)(b * NN + n0) * IP;

    for (int j = threadIdx.x; j < 128 * 36; j += 256) {
        int i = j / 36, c2 = j - (j / 36) * 36;
        float2 v = *(const float2*)(up + i * IP + c2 * 2);
        s[c2 * 2][i] = v.x;
        s[c2 * 2 + 1][i] = v.y;
    }
    __syncthreads();
    for (int j = threadIdx.x; j < IP * 64; j += 256) {
        int c = j / 64, i2 = j - (j / 64) * 64;
        float v0 = s[c][i2 * 2], v1 = s[c][i2 * 2 + 1];
        __nv_bfloat16 h0 = __float2bfloat16(v0);
        __nv_bfloat16 h1 = __float2bfloat16(v1);
        __nv_bfloat16 l0 = __float2bfloat16(v0 - __bfloat162float(h0));
        __nv_bfloat16 l1 = __float2bfloat16(v1 - __bfloat162float(h1));
        unsigned int hp = (unsigned)bf_bits(h0) | ((unsigned)bf_bits(h1) << 16);
        unsigned int lp = (unsigned)bf_bits(l0) | ((unsigned)bf_bits(l1) << 16);
        size_t off = (size_t)(b * IP + c) * NN + n0 + i2 * 2;
        *(unsigned int*)((unsigned short*)d_uTh + off) = hp;
        *(unsigned int*)((unsigned short*)d_uTl + off) = lp;
    }
}

// ---------------- mma.sync bf16x3 GEMM: D[512,4608] = A @ uT^T ----------------
// grid (4, 36), 256 threads (8 warps). CTA tile 128x128, BK=32.
// warp tile 32(m) x 64(n): warp_m = wid&3, warp_n = wid>>2.
#define GBK 32
#define GSTRIDE 40                 // bf16 elems per smem row (80B, conflict-free for ldsm)
#define MAT_E (128 * GSTRIDE)      // 5120 elems per matrix
#define STAGE_E (4 * MAT_E)        // Ah, Al, Bh, Bl

__device__ __forceinline__ void load_stage_g(__nv_bfloat16* s, int m0, int nt0, int k0, int tid) {
    const unsigned short* Ah = (const unsigned short*)d_Ah;
    const unsigned short* Al = (const unsigned short*)d_Al;
    const unsigned short* Bh = (const unsigned short*)d_uTh;
    const unsigned short* Bl = (const unsigned short*)d_uTl;
#pragma unroll
    for (int r = 0; r < 2; r++) {
        int idx = r * 256 + tid;        // 0..511
        int row = idx >> 2, c = idx & 3;
        uint32_t so = smem_u32(s + row * GSTRIDE + c * 8);
        size_t ga = (size_t)(m0 + row) * NN + k0 + c * 8;
        size_t gb = (size_t)(nt0 + row) * NN + k0 + c * 8;
        cp16(so,                Ah + ga);
        cp16(so + MAT_E * 2,    Al + ga);
        cp16(so + MAT_E * 4,    Bh + gb);
        cp16(so + MAT_E * 6,    Bl + gb);
    }
}

__global__ void __launch_bounds__(256, 1) gemm_mma_kernel() {
    extern __shared__ __nv_bfloat16 gsm[];
    int tid = threadIdx.x;
    int wid = tid >> 5, lane = tid & 31;
    int m0 = blockIdx.x * 128;
    int nt0 = blockIdx.y * 128;
    int wm = (wid & 3) * 32;      // warp m offset within tile
    int wn = (wid >> 2) * 64;     // warp n offset within tile

    float acc[2][8][4];
#pragma unroll
    for (int i = 0; i < 2; i++)
#pragma unroll
        for (int j = 0; j < 8; j++)
#pragma unroll
            for (int r = 0; r < 4; r++) acc[i][j][r] = 0.f;

    load_stage_g(gsm, m0, nt0, 0, tid);
    CP_COMMIT();
    load_stage_g(gsm + STAGE_E, m0, nt0, GBK, tid);
    CP_COMMIT();

    // ldmatrix lane addressing pieces
    int lrow = (lane & 7) + ((lane >> 3) & 1) * 8;  // row within 16
    int lcol = (lane >> 4) * 8;                      // 0 or 8

    const int NITER = NN / GBK;  // 16
    for (int it = 0; it < NITER; it++) {
        if (it == NITER - 1) asm volatile("cp.async.wait_group 0;" ::: "memory");
        else                 asm volatile("cp.async.wait_group 1;" ::: "memory");
        __syncthreads();

        __nv_bfloat16* st = gsm + (it & 1) * STAGE_E;
        __nv_bfloat16* sAh = st;
        __nv_bfloat16* sAl = st + MAT_E;
        __nv_bfloat16* sBh = st + 2 * MAT_E;
        __nv_bfloat16* sBl = st + 3 * MAT_E;

#pragma unroll
        for (int kp = 0; kp < GBK; kp += 16) {
            uint32_t ah[2][4], al[2][4], bh[4][4], bl[4][4];
#pragma unroll
            for (int i = 0; i < 2; i++) {
                uint32_t ad = smem_u32(sAh + (wm + i * 16 + lrow) * GSTRIDE + kp + lcol);
                ldsm4(ah[i][0], ah[i][1], ah[i][2], ah[i][3], ad);
                uint32_t ad2 = smem_u32(sAl + (wm + i * 16 + lrow) * GSTRIDE + kp + lcol);
                ldsm4(al[i][0], al[i][1], al[i][2], al[i][3], ad2);
            }
#pragma unroll
            for (int p = 0; p < 4; p++) {
                uint32_t bd = smem_u32(sBh + (wn + p * 16 + lrow) * GSTRIDE + kp + lcol);
                ldsm4(bh[p][0], bh[p][1], bh[p][2], bh[p][3], bd);
                uint32_t bd2 = smem_u32(sBl + (wn + p * 16 + lrow) * GSTRIDE + kp + lcol);
                ldsm4(bl[p][0], bl[p][1], bl[p][2], bl[p][3], bd2);
            }
#pragma unroll
            for (int i = 0; i < 2; i++) {
#pragma unroll
                for (int j = 0; j < 8; j++) {
                    int p = j >> 1, w = j & 1;
                    uint32_t b0h = bh[p][w], b1h = bh[p][w + 2];
                    uint32_t b0l = bl[p][w], b1l = bl[p][w + 2];
                    mma_bf16(acc[i][j], ah[i], b0h, b1h);
                    mma_bf16(acc[i][j], ah[i], b0l, b1l);
                    mma_bf16(acc[i][j], al[i], b0h, b1h);
                }
            }
        }
        __syncthreads();
        if (it + 2 < NITER) {
            load_stage_g(gsm + (it & 1) * STAGE_E, m0, nt0, (it + 2) * GBK, tid);
            CP_COMMIT();
        }
    }

    // epilogue: scatter to d_g[(b*NN + m)*IP + cc]
#pragma unroll
    for (int i = 0; i < 2; i++) {
        int mrow0 = m0 + wm + i * 16 + (lane >> 2);
#pragma unroll
        for (int j = 0; j < 8; j++) {
            int col0 = nt0 + wn + j * 8 + (lane & 3) * 2;
#pragma unroll
            for (int r = 0; r < 4; r++) {
                int m = mrow0 + (r >> 1) * 8;
                unsigned col_g = (unsigned)(col0 + (r & 1));
                unsigned b = col_g / 72u;
                unsigned cc = col_g - b * 72u;
                d_g[((size_t)b * NN + m) * IP + cc] = acc[i][j][r];
            }
        }
    }
}

// ---------------- zr gate ----------------
__global__ void gate_zr_kernel() {
    int n = blockIdx.x;
    __shared__ float sin_[64][133];
    int tid = threadIdx.x;

    for (int idx = tid; idx < 64 * 66; idx += 512) {
        int b = idx / 66, i = idx - b * 66;
        int row = (b * NN + n) * IP;
        sin_[b][i] = d_u[row + i];
        sin_[b][66 + i] = d_g[row + i];
    }
    __syncthreads();

    int bg = tid & 15;
    int og = tid >> 4;
    float4 bias = *((const float4*)(d_bnzr + n * 128) + og);
    float acc[4][4];
#pragma unroll
    for (int j = 0; j < 4; j++) {
        acc[j][0] = bias.x; acc[j][1] = bias.y; acc[j][2] = bias.z; acc[j][3] = bias.w;
    }
    const float4* wp = (const float4*)(d_Wnzr + (size_t)n * KI * 128) + og;
#pragma unroll 4
    for (int ki = 0; ki < KI; ki++) {
        float4 w = wp[ki * 32];
#pragma unroll
        for (int j = 0; j < 4; j++) {
            float uv = sin_[bg + 16 * j][ki];
            acc[j][0] = fmaf(uv, w.x, acc[j][0]);
            acc[j][1] = fmaf(uv, w.y, acc[j][1]);
            acc[j][2] = fmaf(uv, w.z, acc[j][2]);
            acc[j][3] = fmaf(uv, w.w, acc[j][3]);
        }
    }
#pragma unroll
    for (int j = 0; j < 4; j++) {
        int b = bg + 16 * j;
        int row = b * NN + n;
#pragma unroll
        for (int c = 0; c < 4; c++) {
            int o = og * 4 + c;
            float s = 1.f / (1.f + expf(-acc[j][c]));
            if (o < HH) {
                d_z[row * HH + o] = s;
            } else {
                int oo = o - HH;
                d_u2[row * IP + CC + oo] = s * d_h[row * HH + oo];
            }
        }
    }
    if (og == 0) {
#pragma unroll
        for (int j = 0; j < 4; j++) {
            int row = (bg + 16 * j) * NN + n;
            d_u2[row * IP + 0] = d_u[row * IP + 0];
            d_u2[row * IP + 1] = d_u[row * IP + 1];
#pragma unroll
            for (int p = 66; p < IP; p++) d_u2[row * IP + p] = 0.f;
        }
    }
}

// ---------------- candidate gate + state update ----------------
__global__ void gate_c_kernel(const float* __restrict__ x, int t) {
    int n = blockIdx.x;
    __shared__ float sin_[64][133];
    int tid = threadIdx.x;

    for (int idx = tid; idx < 64 * 66; idx += 256) {
        int b = idx / 66, i = idx - b * 66;
        int row = (b * NN + n) * IP;
        sin_[b][i] = d_u2[row + i];
        sin_[b][66 + i] = d_g[row + i];
    }
    __syncthreads();

    int bg = tid & 15;
    int og = tid >> 4;
    float4 bias = *((const float4*)(d_bnc + n * 64) + og);
    float acc[4][4];
#pragma unroll
    for (int j = 0; j < 4; j++) {
        acc[j][0] = bias.x; acc[j][1] = bias.y; acc[j][2] = bias.z; acc[j][3] = bias.w;
    }
    const float4* wp = (const float4*)(d_Wnc + (size_t)n * KI * 64) + og;
#pragma unroll 4
    for (int ki = 0; ki < KI; ki++) {
        float4 w = wp[ki * 16];
#pragma unroll
        for (int j = 0; j < 4; j++) {
            float uv = sin_[bg + 16 * j][ki];
            acc[j][0] = fmaf(uv, w.x, acc[j][0]);
            acc[j][1] = fmaf(uv, w.y, acc[j][1]);
            acc[j][2] = fmaf(uv, w.z, acc[j][2]);
            acc[j][3] = fmaf(uv, w.w, acc[j][3]);
        }
    }
    bool more = (t < TT - 1);
#pragma unroll
    for (int j = 0; j < 4; j++) {
        int b = bg + 16 * j;
        int row = b * NN + n;
#pragma unroll
        for (int c = 0; c < 4; c++) {
            int o = og * 4 + c;
            float hc = tanhf(acc[j][c]);
            float z = d_z[row * HH + o];
            float hn = z * d_h[row * HH + o] + (1.f - z) * hc;
            d_h[row * HH + o] = hn;
            if (more) d_u[row * IP + CC + o] = hn;
        }
    }
    if (og == 0 && more) {
#pragma unroll
        for (int j = 0; j < 4; j++) {
            int b = bg + 16 * j;
            int row = b * NN + n;
            d_u[row * IP + 0] = x[((b * TT + t + 1) * NN + n) * CC + 0];
            d_u[row * IP + 1] = x[((b * TT + t + 1) * NN + n) * CC + 1];
        }
    }
}

// ---------------- readout ----------------
__global__ void readout_kernel(const float* __restrict__ Wout,
                               const float* __restrict__ bout,
                               float* __restrict__ out) {
    int idx = blockIdx.x * blockDim.x + threadIdx.x;
    if (idx >= BB * NN) return;
    float s = bout[0];
    const float* hp = d_h + (size_t)idx * HH;
#pragma unroll
    for (int o = 0; o < HH; o++) s = fmaf(hp[o], Wout[o], s);
    out[idx] = s;
}

// ---------------- launch ----------------
extern "C" void kernel_launch(void* const* d_in, const int* in_sizes, int n_in,
                              void* d_out, int out_size) {
    const float* x    = (const float*)d_in[0];
    const float* E1   = (const float*)d_in[1];
    const float* Wzr  = (const float*)d_in[2];
    const float* bzr  = (const float*)d_in[3];
    const float* Wc   = (const float*)d_in[4];
    const float* bc   = (const float*)d_in[5];
    const float* Wout = (const float*)d_in[6];
    const float* bout = (const float*)d_in[7];
    float* out = (float*)d_out;

    const int GEMM_SMEM = 2 * STAGE_E * 2;  // bytes: 2 stages x 40960 B
    cudaFuncSetAttribute(gemm_mma_kernel,
                         cudaFuncAttributeMaxDynamicSharedMemorySize, GEMM_SMEM);

    compute_A_kernel<<<NN, 256>>>(E1);
    {
        int tot0 = NN * KI * 128;
        mix_pool_kernel<<<(tot0 + 255) / 256, 256>>>(Wzr, E1, 0, KI * 128, tot0);
        int tot1 = NN * KI * 64;
        mix_pool_kernel<<<(tot1 + 255) / 256, 256>>>(Wc, E1, 1, KI * 64, tot1);
        mix_pool_kernel<<<(NN * 128 + 255) / 256, 256>>>(bzr, E1, 2, 128, NN * 128);
        mix_pool_kernel<<<(NN * 64 + 255) / 256, 256>>>(bc, E1, 3, 64, NN * 64);
    }
    init_kernel<<<(BB * NN * IP + 255) / 256, 256>>>(x);

    dim3 tgrid(4, BB);
    dim3 ggrid(4, NT / 128);
    for (int t = 0; t < TT; t++) {
        transpose_kernel<<<tgrid, 256>>>(0);
        gemm_mma_kernel<<<ggrid, 256, GEMM_SMEM>>>();
        gate_zr_kernel<<<NN, 512>>>();
        transpose_kernel<<<tgrid, 256>>>(1);
        gemm_mma_kernel<<<ggrid, 256, GEMM_SMEM>>>();
        gate_c_kernel<<<NN, 256>>>(x, t);
    }

    readout_kernel<<<(BB * NN + 255) / 256, 256>>>(Wout, bout, out);
}

// round 4
// speedup vs baseline: 3.2065x; 2.1072x over previous
#include <cuda_runtime.h>
#include <cuda_bf16.h>
#include <math.h>
#include <stdint.h>

// Problem dims
#define BB 64
#define TT 24
#define NN 512
#define CC 2
#define HH 64
#define DD 16
#define II 66       // C + H
#define KIP 144     // padded gate K (2*66 -> 144)
#define JP 72       // padded per-batch column width
#define NT (BB*JP)  // 4608 GEMM columns (b,c)

// ---------------- device scratch ----------------
__device__ __nv_bfloat16 d_Ah[NN * NN];
__device__ __nv_bfloat16 d_Al[NN * NN];
__device__ __nv_bfloat16 d_uTh[NN * NT];    // [n][(b,c)] = u[b][n][c] hi
__device__ __nv_bfloat16 d_uTl[NN * NT];
__device__ __nv_bfloat16 d_u2Th[NN * NT];
__device__ __nv_bfloat16 d_u2Tl[NN * NT];
__device__ float d_gT[NN * NT];             // [n][(b,c)] GEMM output
__device__ float d_hT[NN * BB * HH];        // [n][(b,o)]
__device__ float d_zT[NN * BB * HH];        // [n][(b,o)]
__device__ __nv_bfloat16 d_Wzrh[NN * KIP * 128];  // [n][ki][o]
__device__ __nv_bfloat16 d_Wzrl[NN * KIP * 128];
__device__ __nv_bfloat16 d_Wch[NN * KIP * 64];
__device__ __nv_bfloat16 d_Wcl[NN * KIP * 64];
__device__ float d_bnzr[NN * 128];
__device__ float d_bnc[NN * 64];

// ---------------- helpers ----------------
__device__ __forceinline__ uint32_t smem_u32(const void* p) {
    uint32_t a;
    asm("{ .reg .u64 t; cvta.to.shared.u64 t, %1; cvt.u32.u64 %0, t; }" : "=r"(a) : "l"(p));
    return a;
}
__device__ __forceinline__ void cp16(uint32_t saddr, const void* g) {
    asm volatile("cp.async.cg.shared.global [%0], [%1], 16;" :: "r"(saddr), "l"(g));
}
#define CP_COMMIT() asm volatile("cp.async.commit_group;" ::: "memory")

__device__ __forceinline__ void ldsm4(uint32_t& r0, uint32_t& r1, uint32_t& r2, uint32_t& r3,
                                      uint32_t addr) {
    asm volatile("ldmatrix.sync.aligned.m8n8.x4.shared.b16 {%0,%1,%2,%3}, [%4];"
                 : "=r"(r0), "=r"(r1), "=r"(r2), "=r"(r3) : "r"(addr));
}
__device__ __forceinline__ void ldsm4t(uint32_t& r0, uint32_t& r1, uint32_t& r2, uint32_t& r3,
                                       uint32_t addr) {
    asm volatile("ldmatrix.sync.aligned.m8n8.x4.trans.shared.b16 {%0,%1,%2,%3}, [%4];"
                 : "=r"(r0), "=r"(r1), "=r"(r2), "=r"(r3) : "r"(addr));
}
__device__ __forceinline__ void mma_bf16(float* c, const uint32_t* a, uint32_t b0, uint32_t b1) {
    asm volatile(
        "mma.sync.aligned.m16n8k16.row.col.f32.bf16.bf16.f32 "
        "{%0,%1,%2,%3}, {%4,%5,%6,%7}, {%8,%9}, {%0,%1,%2,%3};"
        : "+f"(c[0]), "+f"(c[1]), "+f"(c[2]), "+f"(c[3])
        : "r"(a[0]), "r"(a[1]), "r"(a[2]), "r"(a[3]), "r"(b0), "r"(b1));
}
__device__ __forceinline__ void bf_split(float f, __nv_bfloat16& h, __nv_bfloat16& l) {
    h = __float2bfloat16(f);
    l = __float2bfloat16(f - __bfloat162float(h));
}

// ================= setup kernels =================

// A = softmax(relu(E1 E1^T)), bf16 hi/lo
__global__ void compute_A_kernel(const float* __restrict__ E1) {
    int n = blockIdx.x;
    __shared__ float en[DD];
    __shared__ float red[256];
    int tid = threadIdx.x;
    if (tid < DD) en[tid] = E1[n * DD + tid];
    __syncthreads();
    float v[2];
#pragma unroll
    for (int j = 0; j < 2; j++) {
        const float* em = E1 + (tid + j * 256) * DD;
        float s = 0.f;
#pragma unroll
        for (int d = 0; d < DD; d++) s = fmaf(en[d], em[d], s);
        v[j] = fmaxf(s, 0.f);
    }
    red[tid] = fmaxf(v[0], v[1]);
    __syncthreads();
    for (int s = 128; s > 0; s >>= 1) {
        if (tid < s) red[tid] = fmaxf(red[tid], red[tid + s]);
        __syncthreads();
    }
    float mx = red[0];
    __syncthreads();
    float e0 = expf(v[0] - mx), e1 = expf(v[1] - mx);
    red[tid] = e0 + e1;
    __syncthreads();
    for (int s = 128; s > 0; s >>= 1) {
        if (tid < s) red[tid] += red[tid + s];
        __syncthreads();
    }
    float inv = 1.f / red[0];
    __nv_bfloat16 h, l;
    bf_split(e0 * inv, h, l);
    d_Ah[n * NN + tid] = h; d_Al[n * NN + tid] = l;
    bf_split(e1 * inv, h, l);
    d_Ah[n * NN + tid + 256] = h; d_Al[n * NN + tid + 256] = l;
}

// node-adaptive zr weights: [n][ki][o=128], bf16 hi/lo, ki padded to 144
__global__ void mix_w_zr_kernel(const float* __restrict__ pool, const float* __restrict__ E1) {
    int idx = blockIdx.x * blockDim.x + threadIdx.x;
    if (idx >= NN * KIP * 128) return;
    int o = idx & 127;
    int ki = (idx >> 7) % KIP;
    int n = idx / (KIP * 128);
    float s = 0.f;
    if (ki < 132) {
        int k = ki / 66, i = ki - k * 66;
        const float* p = pool + ((k * 66 + i) * 128) + o;   // [d][k][i][o], step d = 2*66*128
#pragma unroll
        for (int d = 0; d < DD; d++)
            s = fmaf(E1[n * DD + d], p[d * 2 * 66 * 128], s);
    }
    __nv_bfloat16 h, l;
    bf_split(s, h, l);
    d_Wzrh[idx] = h; d_Wzrl[idx] = l;
}

__global__ void mix_w_c_kernel(const float* __restrict__ pool, const float* __restrict__ E1) {
    int idx = blockIdx.x * blockDim.x + threadIdx.x;
    if (idx >= NN * KIP * 64) return;
    int o = idx & 63;
    int ki = (idx >> 6) % KIP;
    int n = idx / (KIP * 64);
    float s = 0.f;
    if (ki < 132) {
        int k = ki / 66, i = ki - k * 66;
        const float* p = pool + ((k * 66 + i) * 64) + o;
#pragma unroll
        for (int d = 0; d < DD; d++)
            s = fmaf(E1[n * DD + d], p[d * 2 * 66 * 64], s);
    }
    __nv_bfloat16 h, l;
    bf_split(s, h, l);
    d_Wch[idx] = h; d_Wcl[idx] = l;
}

// biases (fp32)
__global__ void mix_bias_kernel(const float* __restrict__ bzr, const float* __restrict__ bc,
                                const float* __restrict__ E1) {
    int idx = blockIdx.x * blockDim.x + threadIdx.x;
    if (idx < NN * 128) {
        int n = idx >> 7, o = idx & 127;
        float s = 0.f;
#pragma unroll
        for (int d = 0; d < DD; d++) s = fmaf(E1[n * DD + d], bzr[d * 128 + o], s);
        d_bnzr[idx] = s;
    } else if (idx < NN * 128 + NN * 64) {
        int i2 = idx - NN * 128;
        int n = i2 >> 6, o = i2 & 63;
        float s = 0.f;
#pragma unroll
        for (int d = 0; d < DD; d++) s = fmaf(E1[n * DD + d], bc[d * 64 + o], s);
        d_bnc[i2] = s;
    }
}

// init: uT = [x_0, 0], u2T zero, hT zero
__global__ void init_kernel(const float* __restrict__ x) {
    int n = blockIdx.y;
    int j = blockIdx.x * 256 + threadIdx.x;  // 0..4607
    int b = j / JP, c = j - b * JP;
    float f = (c < CC) ? x[((size_t)(b * TT) * NN + n) * CC + c] : 0.f;
    __nv_bfloat16 h, l;
    bf_split(f, h, l);
    size_t o = (size_t)n * NT + j;
    d_uTh[o] = h; d_uTl[o] = l;
    d_u2Th[o] = __float2bfloat16(0.f);
    d_u2Tl[o] = __float2bfloat16(0.f);
    if (j < BB * HH) d_hT[(size_t)n * BB * HH + j] = 0.f;
}

// ================= GEMM: gT[512,4608] = A @ uT (bf16x3) =================
// grid (4 m-tiles, 36 j-tiles), 256 threads. CTA tile 128x128, BK=32.
#define G_AH 0
#define G_AL 5120
#define G_BH 10240
#define G_BL 14592
#define G_STAGE 18944   // elems per stage

__device__ __forceinline__ void load_stage_g(__nv_bfloat16* s, int m0, int nt0, int k0, int tid,
                                             const __nv_bfloat16* Bh, const __nv_bfloat16* Bl) {
#pragma unroll
    for (int r = 0; r < 2; r++) {     // A: 128 rows x 32 k
        int idx = r * 256 + tid;
        int row = idx >> 2, c = idx & 3;
        uint32_t so = smem_u32(s + row * 40 + c * 8);
        size_t ga = (size_t)(m0 + row) * NN + k0 + c * 8;
        cp16(so, d_Ah + ga);
        cp16(so + G_AL * 2, d_Al + ga);
    }
#pragma unroll
    for (int r = 0; r < 2; r++) {     // B: 32 k-rows x 128 j
        int idx = r * 256 + tid;
        int row = idx >> 4, c = idx & 15;
        uint32_t so = smem_u32(s + G_BH + row * 136 + c * 8);
        size_t gb = (size_t)(k0 + row) * NT + nt0 + c * 8;
        cp16(so, Bh + gb);
        cp16(so + 4352 * 2, Bl + gb);
    }
}

__global__ void __launch_bounds__(256, 1) gemm_tc_kernel(int use_u2) {
    extern __shared__ __nv_bfloat16 dsm[];
    const __nv_bfloat16* Bh = use_u2 ? d_u2Th : d_uTh;
    const __nv_bfloat16* Bl = use_u2 ? d_u2Tl : d_uTl;
    int tid = threadIdx.x;
    int wid = tid >> 5, lane = tid & 31;
    int m0 = blockIdx.x * 128;
    int nt0 = blockIdx.y * 128;
    int wm = (wid & 3) * 32;
    int wn = (wid >> 2) * 64;
    int lrow = lane & 15, lcol = (lane >> 4) * 8;

    float acc[2][8][4];
#pragma unroll
    for (int i = 0; i < 2; i++)
#pragma unroll
        for (int t = 0; t < 8; t++)
#pragma unroll
            for (int r = 0; r < 4; r++) acc[i][t][r] = 0.f;

    load_stage_g(dsm, m0, nt0, 0, tid, Bh, Bl);
    CP_COMMIT();
    load_stage_g(dsm + G_STAGE, m0, nt0, 32, tid, Bh, Bl);
    CP_COMMIT();

    const int NITER = NN / 32;  // 16
    for (int it = 0; it < NITER; it++) {
        if (it == NITER - 1) asm volatile("cp.async.wait_group 0;" ::: "memory");
        else                 asm volatile("cp.async.wait_group 1;" ::: "memory");
        __syncthreads();
        __nv_bfloat16* st = dsm + (it & 1) * G_STAGE;

#pragma unroll
        for (int kp = 0; kp < 32; kp += 16) {
            uint32_t ah[2][4], al[2][4], bh[4][4], bl[4][4];
#pragma unroll
            for (int i = 0; i < 2; i++) {
                uint32_t ad = smem_u32(st + (wm + i * 16 + lrow) * 40 + kp + lcol);
                ldsm4(ah[i][0], ah[i][1], ah[i][2], ah[i][3], ad);
                ldsm4(al[i][0], al[i][1], al[i][2], al[i][3], ad + G_AL * 2);
            }
#pragma unroll
            for (int p = 0; p < 4; p++) {
                uint32_t bd = smem_u32(st + G_BH + (kp + lrow) * 136 + wn + p * 16 + lcol);
                ldsm4t(bh[p][0], bh[p][1], bh[p][2], bh[p][3], bd);
                ldsm4t(bl[p][0], bl[p][1], bl[p][2], bl[p][3], bd + 4352 * 2);
            }
#pragma unroll
            for (int i = 0; i < 2; i++) {
#pragma unroll
                for (int t = 0; t < 8; t++) {
                    int p = t >> 1, hf = t & 1;
                    uint32_t b0h = bh[p][hf * 2], b1h = bh[p][hf * 2 + 1];
                    uint32_t b0l = bl[p][hf * 2], b1l = bl[p][hf * 2 + 1];
                    mma_bf16(acc[i][t], ah[i], b0h, b1h);
                    mma_bf16(acc[i][t], ah[i], b0l, b1l);
                    mma_bf16(acc[i][t], al[i], b0h, b1h);
                }
            }
        }
        __syncthreads();
        if (it + 2 < NITER) {
            load_stage_g(dsm + (it & 1) * G_STAGE, m0, nt0, (it + 2) * 32, tid, Bh, Bl);
            CP_COMMIT();
        }
    }

    // epilogue: contiguous float2 stores to gT rows
#pragma unroll
    for (int i = 0; i < 2; i++) {
        int mr = m0 + wm + i * 16 + (lane >> 2);
#pragma unroll
        for (int t = 0; t < 8; t++) {
            int p = t >> 1, hf = t & 1;
            int col = nt0 + wn + p * 16 + hf * 8 + (lane & 3) * 2;
            float2 v0 = make_float2(acc[i][t][0], acc[i][t][1]);
            float2 v1 = make_float2(acc[i][t][2], acc[i][t][3]);
            *(float2*)(d_gT + (size_t)mr * NT + col) = v0;
            *(float2*)(d_gT + (size_t)(mr + 8) * NT + col) = v1;
        }
    }
}

// ================= gate zr: per-node MMA 64x128xK144, bf16x3 =================
// smem (elems): sAh [64][152] @0, sAl @9728, W stages @19456: [2][2][16][136]
#define ZR_SA 9728
#define ZR_SW 19456
#define ZR_WSTAGE 4352
#define ZR_WH 2176

__device__ __forceinline__ void zr_fill_w(__nv_bfloat16* dsm, int n, int chunk, int stage, int tid) {
#pragma unroll
    for (int j = 0; j < 2; j++) {
        int idx = j * 256 + tid;          // 0..511
        int h = idx >> 8;                 // 0 hi, 1 lo
        int rem = idx & 255;
        int row = rem >> 4, cc = rem & 15;
        uint32_t so = smem_u32(dsm + ZR_SW + stage * ZR_WSTAGE + h * ZR_WH + row * 136 + cc * 8);
        size_t ga = ((size_t)n * KIP + chunk * 16 + row) * 128 + cc * 8;
        cp16(so, (h ? d_Wzrl : d_Wzrh) + ga);
    }
}

__global__ void __launch_bounds__(256, 2) gate_zr_kernel() {
    extern __shared__ __nv_bfloat16 dsm[];
    int n = blockIdx.x;
    int tid = threadIdx.x;
    int wid = tid >> 5, lane = tid & 31;
    int wm16 = (wid & 3) * 16;
    int wn2 = wid >> 2;
    int lrow = lane & 15, lcol = (lane >> 4) * 8;

    // copy x part of uT -> u2T (pads stay zero from init)
    if (tid < 64) {
        size_t o = (size_t)n * NT + tid * JP;
        d_u2Th[o] = d_uTh[o]; d_u2Th[o + 1] = d_uTh[o + 1];
        d_u2Tl[o] = d_uTl[o]; d_u2Tl[o + 1] = d_uTl[o + 1];
    }

    zr_fill_w(dsm, n, 0, 0, tid);
    CP_COMMIT();

    // activations: [x,h]=uT (bf16 direct), g=gT (fp32 split); pad ki>=132 zero
    for (int idx = tid; idx < 64 * KIP; idx += 256) {
        int b = idx / KIP, ki = idx - b * KIP;
        __nv_bfloat16 h, l;
        if (ki < 66) {
            size_t a = (size_t)n * NT + b * JP + ki;
            h = d_uTh[a]; l = d_uTl[a];
        } else if (ki < 132) {
            bf_split(d_gT[(size_t)n * NT + b * JP + ki - 66], h, l);
        } else {
            h = __float2bfloat16(0.f); l = h;
        }
        dsm[b * 152 + ki] = h;
        dsm[ZR_SA + b * 152 + ki] = l;
    }

    zr_fill_w(dsm, n, 1, 1, tid);
    CP_COMMIT();

    float acc[8][4];
#pragma unroll
    for (int t = 0; t < 8; t++)
#pragma unroll
        for (int r = 0; r < 4; r++) acc[t][r] = 0.f;

    for (int c = 0; c < 9; c++) {
        if (c == 8) asm volatile("cp.async.wait_group 0;" ::: "memory");
        else        asm volatile("cp.async.wait_group 1;" ::: "memory");
        __syncthreads();
        __nv_bfloat16* w = dsm + ZR_SW + (c & 1) * ZR_WSTAGE;

        uint32_t ah[4], al[4], bh[4][4], bl[4][4];
        uint32_t ad = smem_u32(dsm + (wm16 + lrow) * 152 + c * 16 + lcol);
        ldsm4(ah[0], ah[1], ah[2], ah[3], ad);
        ldsm4(al[0], al[1], al[2], al[3], ad + ZR_SA * 2);
#pragma unroll
        for (int p = 0; p < 4; p++) {
            uint32_t bd = smem_u32(w + lrow * 136 + wn2 * 64 + p * 16 + lcol);
            ldsm4t(bh[p][0], bh[p][1], bh[p][2], bh[p][3], bd);
            ldsm4t(bl[p][0], bl[p][1], bl[p][2], bl[p][3], bd + ZR_WH * 2);
        }
#pragma unroll
        for (int t = 0; t < 8; t++) {
            int p = t >> 1, hf = t & 1;
            uint32_t b0h = bh[p][hf * 2], b1h = bh[p][hf * 2 + 1];
            uint32_t b0l = bl[p][hf * 2], b1l = bl[p][hf * 2 + 1];
            mma_bf16(acc[t], ah, b0h, b1h);
            mma_bf16(acc[t], ah, b0l, b1l);
            mma_bf16(acc[t], al, b0h, b1h);
        }
        __syncthreads();
        if (c + 2 < 9) {
            zr_fill_w(dsm, n, c + 2, c & 1, tid);
            CP_COMMIT();
        }
    }

    // epilogue: wn2==0 -> z (o 0..63); wn2==1 -> r*h -> u2T
    const float* bias = d_bnzr + n * 128;
#pragma unroll
    for (int t = 0; t < 8; t++) {
        int p = t >> 1, hf = t & 1;
        int oc = wn2 * 64 + p * 16 + hf * 8 + (lane & 3) * 2;
        float bi0 = bias[oc], bi1 = bias[oc + 1];
#pragma unroll
        for (int rr = 0; rr < 2; rr++) {
            int b = wm16 + (lane >> 2) + rr * 8;
            float s0 = 1.f / (1.f + __expf(-(acc[t][rr * 2] + bi0)));
            float s1 = 1.f / (1.f + __expf(-(acc[t][rr * 2 + 1] + bi1)));
            if (wn2 == 0) {
                *(float2*)(d_zT + (size_t)n * BB * HH + b * HH + oc) = make_float2(s0, s1);
            } else {
                int oo = oc - 64;
                size_t hb = (size_t)n * BB * HH + b * HH + oo;
                float r0 = s0 * d_hT[hb];
                float r1 = s1 * d_hT[hb + 1];
                __nv_bfloat16 h, l;
                size_t ub = (size_t)n * NT + b * JP + 2 + oo;
                bf_split(r0, h, l);
                d_u2Th[ub] = h; d_u2Tl[ub] = l;
                bf_split(r1, h, l);
                d_u2Th[ub + 1] = h; d_u2Tl[ub + 1] = l;
            }
        }
    }
}

// ================= gate c: per-node MMA 64x64xK144 + GRU update =================
#define C_SW 19456
#define C_WSTAGE 2304
#define C_WH 1152

__device__ __forceinline__ void c_fill_w(__nv_bfloat16* dsm, int n, int chunk, int stage, int tid) {
    int h = tid >> 7;
    int rem = tid & 127;
    int row = rem >> 3, cc = rem & 7;
    uint32_t so = smem_u32(dsm + C_SW + stage * C_WSTAGE + h * C_WH + row * 72 + cc * 8);
    size_t ga = ((size_t)n * KIP + chunk * 16 + row) * 64 + cc * 8;
    cp16(so, (h ? d_Wcl : d_Wch) + ga);
}

__global__ void __launch_bounds__(256, 2) gate_c_kernel(const float* __restrict__ x, int t) {
    extern __shared__ __nv_bfloat16 dsm[];
    int n = blockIdx.x;
    int tid = threadIdx.x;
    int wid = tid >> 5, lane = tid & 31;
    int wm16 = (wid & 3) * 16;
    int wn2 = wid >> 2;
    int lrow = lane & 15, lcol = (lane >> 4) * 8;
    bool more = (t < TT - 1);

    c_fill_w(dsm, n, 0, 0, tid);
    CP_COMMIT();

    for (int idx = tid; idx < 64 * KIP; idx += 256) {
        int b = idx / KIP, ki = idx - b * KIP;
        __nv_bfloat16 h, l;
        if (ki < 66) {
            size_t a = (size_t)n * NT + b * JP + ki;
            h = d_u2Th[a]; l = d_u2Tl[a];
        } else if (ki < 132) {
            bf_split(d_gT[(size_t)n * NT + b * JP + ki - 66], h, l);
        } else {
            h = __float2bfloat16(0.f); l = h;
        }
        dsm[b * 152 + ki] = h;
        dsm[ZR_SA + b * 152 + ki] = l;
    }

    c_fill_w(dsm, n, 1, 1, tid);
    CP_COMMIT();

    float acc[4][4];
#pragma unroll
    for (int t2 = 0; t2 < 4; t2++)
#pragma unroll
        for (int r = 0; r < 4; r++) acc[t2][r] = 0.f;

    for (int c = 0; c < 9; c++) {
        if (c == 8) asm volatile("cp.async.wait_group 0;" ::: "memory");
        else        asm volatile("cp.async.wait_group 1;" ::: "memory");
        __syncthreads();
        __nv_bfloat16* w = dsm + C_SW + (c & 1) * C_WSTAGE;

        uint32_t ah[4], al[4], bh[2][4], bl[2][4];
        uint32_t ad = smem_u32(dsm + (wm16 + lrow) * 152 + c * 16 + lcol);
        ldsm4(ah[0], ah[1], ah[2], ah[3], ad);
        ldsm4(al[0], al[1], al[2], al[3], ad + ZR_SA * 2);
#pragma unroll
        for (int p = 0; p < 2; p++) {
            uint32_t bd = smem_u32(w + lrow * 72 + wn2 * 32 + p * 16 + lcol);
            ldsm4t(bh[p][0], bh[p][1], bh[p][2], bh[p][3], bd);
            ldsm4t(bl[p][0], bl[p][1], bl[p][2], bl[p][3], bd + C_WH * 2);
        }
#pragma unroll
        for (int t2 = 0; t2 < 4; t2++) {
            int p = t2 >> 1, hf = t2 & 1;
            uint32_t b0h = bh[p][hf * 2], b1h = bh[p][hf * 2 + 1];
            uint32_t b0l = bl[p][hf * 2], b1l = bl[p][hf * 2 + 1];
            mma_bf16(acc[t2], ah, b0h, b1h);
            mma_bf16(acc[t2], ah, b0l, b1l);
            mma_bf16(acc[t2], al, b0h, b1h);
        }
        __syncthreads();
        if (c + 2 < 9) {
            c_fill_w(dsm, n, c + 2, c & 1, tid);
            CP_COMMIT();
        }
    }

    // epilogue: GRU update
    const float* bias = d_bnc + n * 64;
#pragma unroll
    for (int t2 = 0; t2 < 4; t2++) {
        int p = t2 >> 1, hf = t2 & 1;
        int oc = wn2 * 32 + p * 16 + hf * 8 + (lane & 3) * 2;
        float bi0 = bias[oc], bi1 = bias[oc + 1];
#pragma unroll
        for (int rr = 0; rr < 2; rr++) {
            int b = wm16 + (lane >> 2) + rr * 8;
            float hc0 = tanhf(acc[t2][rr * 2] + bi0);
            float hc1 = tanhf(acc[t2][rr * 2 + 1] + bi1);
            size_t hb = (size_t)n * BB * HH + b * HH + oc;
            float z0 = d_zT[hb], z1 = d_zT[hb + 1];
            float hn0 = z0 * d_hT[hb] + (1.f - z0) * hc0;
            float hn1 = z1 * d_hT[hb + 1] + (1.f - z1) * hc1;
            d_hT[hb] = hn0;
            d_hT[hb + 1] = hn1;
            if (more) {
                __nv_bfloat16 h, l;
                size_t ub = (size_t)n * NT + b * JP + 2 + oc;
                bf_split(hn0, h, l);
                d_uTh[ub] = h; d_uTl[ub] = l;
                bf_split(hn1, h, l);
                d_uTh[ub + 1] = h; d_uTl[ub + 1] = l;
            }
        }
    }
    // next x into uT
    if (more && tid < 64) {
        int b = tid;
        size_t ub = (size_t)n * NT + b * JP;
#pragma unroll
        for (int c2 = 0; c2 < CC; c2++) {
            float f = x[((size_t)(b * TT + t + 1) * NN + n) * CC + c2];
            __nv_bfloat16 h, l;
            bf_split(f, h, l);
            d_uTh[ub + c2] = h; d_uTl[ub + c2] = l;
        }
    }
}

// ================= readout =================
__global__ void readout_kernel(const float* __restrict__ Wout,
                               const float* __restrict__ bout,
                               float* __restrict__ out) {
    __shared__ float w[HH];
    int n = blockIdx.x;
    int b = threadIdx.x;  // 64
    if (b < HH) w[b] = Wout[b];
    __syncthreads();
    const float4* hp = (const float4*)(d_hT + (size_t)n * BB * HH + b * HH);
    float s = bout[0];
#pragma unroll
    for (int q = 0; q < HH / 4; q++) {
        float4 v = hp[q];
        s = fmaf(v.x, w[q * 4 + 0], s);
        s = fmaf(v.y, w[q * 4 + 1], s);
        s = fmaf(v.z, w[q * 4 + 2], s);
        s = fmaf(v.w, w[q * 4 + 3], s);
    }
    out[b * NN + n] = s;
}

// ================= launch =================
extern "C" void kernel_launch(void* const* d_in, const int* in_sizes, int n_in,
                              void* d_out, int out_size) {
    const float* x    = (const float*)d_in[0];
    const float* E1   = (const float*)d_in[1];
    const float* Wzr  = (const float*)d_in[2];
    const float* bzr  = (const float*)d_in[3];
    const float* Wc   = (const float*)d_in[4];
    const float* bc   = (const float*)d_in[5];
    const float* Wout = (const float*)d_in[6];
    const float* bout = (const float*)d_in[7];
    float* out = (float*)d_out;

    const int GEMM_SMEM = 2 * G_STAGE * 2;         // 75776 B
    const int ZR_SMEM = (ZR_SW + 2 * ZR_WSTAGE) * 2;  // 56320 B
    const int C_SMEM = (C_SW + 2 * C_WSTAGE) * 2;     // 48128 B
    cudaFuncSetAttribute(gemm_tc_kernel, cudaFuncAttributeMaxDynamicSharedMemorySize, GEMM_SMEM);
    cudaFuncSetAttribute(gate_zr_kernel, cudaFuncAttributeMaxDynamicSharedMemorySize, ZR_SMEM);
    cudaFuncSetAttribute(gate_c_kernel, cudaFuncAttributeMaxDynamicSharedMemorySize, C_SMEM);

    compute_A_kernel<<<NN, 256>>>(E1);                                    // 1
    mix_w_zr_kernel<<<(NN * KIP * 128 + 255) / 256, 256>>>(Wzr, E1);      // 2
    mix_w_c_kernel<<<(NN * KIP * 64 + 255) / 256, 256>>>(Wc, E1);         // 3
    mix_bias_kernel<<<(NN * 192 + 255) / 256, 256>>>(bzr, bc, E1);        // 4
    {
        dim3 ig(NT / 256, NN);
        init_kernel<<<ig, 256>>>(x);                                      // 5
    }

    dim3 ggrid(4, NT / 128);
    for (int t = 0; t < TT; t++) {
        gemm_tc_kernel<<<ggrid, 256, GEMM_SMEM>>>(0);                     // 6 at t=0
        gate_zr_kernel<<<NN, 256, ZR_SMEM>>>();
        gemm_tc_kernel<<<ggrid, 256, GEMM_SMEM>>>(1);
        gate_c_kernel<<<NN, 256, C_SMEM>>>(x, t);
    }

    readout_kernel<<<NN, 64>>>(Wout, bout, out);
}

// round 6
// speedup vs baseline: 4.3184x; 1.3468x over previous
#include <cuda_runtime.h>
#include <cuda_bf16.h>
#include <math.h>
#include <stdint.h>

// Problem dims
#define BB 64
#define TT 24
#define NN 512
#define CC 2
#define HH 64
#define DD 16
#define JP 72        // padded per-batch column width
#define NT (BB*JP)   // 4608 GEMM columns (b,c)
#define KIP2 160     // gate K layout: [u:72 | g:72 | pad:16]

// ---------------- device scratch ----------------
__device__ __nv_bfloat16 d_Ah[NN * NN];
__device__ __nv_bfloat16 d_Al[NN * NN];
__device__ __nv_bfloat16 d_uTh[NN * NT];    // [n][(b,c)]
__device__ __nv_bfloat16 d_uTl[NN * NT];
__device__ __nv_bfloat16 d_u2Th[NN * NT];
__device__ __nv_bfloat16 d_u2Tl[NN * NT];
__device__ __nv_bfloat16 d_gTh[NN * NT];    // GEMM output, bf16 hi/lo
__device__ __nv_bfloat16 d_gTl[NN * NT];
__device__ float d_hT[NN * BB * HH];        // [n][(b,o)]
__device__ float d_zT[NN * BB * HH];
__device__ __nv_bfloat16 d_Wzrh[NN * KIP2 * 128];  // [n][ki:160][o]
__device__ __nv_bfloat16 d_Wzrl[NN * KIP2 * 128];
__device__ __nv_bfloat16 d_Wch[NN * KIP2 * 64];
__device__ __nv_bfloat16 d_Wcl[NN * KIP2 * 64];
__device__ float d_bnzr[NN * 128];
__device__ float d_bnc[NN * 64];

// ---------------- helpers ----------------
__device__ __forceinline__ uint32_t smem_u32(const void* p) {
    uint32_t a;
    asm("{ .reg .u64 t; cvta.to.shared.u64 t, %1; cvt.u32.u64 %0, t; }" : "=r"(a) : "l"(p));
    return a;
}
__device__ __forceinline__ void cp16(uint32_t saddr, const void* g) {
    asm volatile("cp.async.cg.shared.global [%0], [%1], 16;" :: "r"(saddr), "l"(g));
}
#define CP_COMMIT() asm volatile("cp.async.commit_group;" ::: "memory")

__device__ __forceinline__ void ldsm4(uint32_t& r0, uint32_t& r1, uint32_t& r2, uint32_t& r3,
                                      uint32_t addr) {
    asm volatile("ldmatrix.sync.aligned.m8n8.x4.shared.b16 {%0,%1,%2,%3}, [%4];"
                 : "=r"(r0), "=r"(r1), "=r"(r2), "=r"(r3) : "r"(addr));
}
__device__ __forceinline__ void ldsm4t(uint32_t& r0, uint32_t& r1, uint32_t& r2, uint32_t& r3,
                                       uint32_t addr) {
    asm volatile("ldmatrix.sync.aligned.m8n8.x4.trans.shared.b16 {%0,%1,%2,%3}, [%4];"
                 : "=r"(r0), "=r"(r1), "=r"(r2), "=r"(r3) : "r"(addr));
}
__device__ __forceinline__ void mma_bf16(float* c, const uint32_t* a, uint32_t b0, uint32_t b1) {
    asm volatile(
        "mma.sync.aligned.m16n8k16.row.col.f32.bf16.bf16.f32 "
        "{%0,%1,%2,%3}, {%4,%5,%6,%7}, {%8,%9}, {%0,%1,%2,%3};"
        : "+f"(c[0]), "+f"(c[1]), "+f"(c[2]), "+f"(c[3])
        : "r"(a[0]), "r"(a[1]), "r"(a[2]), "r"(a[3]), "r"(b0), "r"(b1));
}
__device__ __forceinline__ void bf_split(float f, __nv_bfloat16& h, __nv_bfloat16& l) {
    h = __float2bfloat16(f);
    l = __float2bfloat16(f - __bfloat162float(h));
}
__device__ __forceinline__ unsigned short bfb(__nv_bfloat16 h) {
    return *reinterpret_cast<unsigned short*>(&h);
}
__device__ __forceinline__ uint32_t pack_split(float a, float b, uint32_t& lo) {
    __nv_bfloat16 h0, l0, h1, l1;
    bf_split(a, h0, l0); bf_split(b, h1, l1);
    lo = (uint32_t)bfb(l0) | ((uint32_t)bfb(l1) << 16);
    return (uint32_t)bfb(h0) | ((uint32_t)bfb(h1) << 16);
}

// ================= setup =================

__global__ void compute_A_kernel(const float* __restrict__ E1) {
    int n = blockIdx.x;
    __shared__ float en[DD];
    __shared__ float red[256];
    int tid = threadIdx.x;
    if (tid < DD) en[tid] = E1[n * DD + tid];
    __syncthreads();
    float v[2];
#pragma unroll
    for (int j = 0; j < 2; j++) {
        const float* em = E1 + (tid + j * 256) * DD;
        float s = 0.f;
#pragma unroll
        for (int d = 0; d < DD; d++) s = fmaf(en[d], em[d], s);
        v[j] = fmaxf(s, 0.f);
    }
    red[tid] = fmaxf(v[0], v[1]);
    __syncthreads();
    for (int s = 128; s > 0; s >>= 1) {
        if (tid < s) red[tid] = fmaxf(red[tid], red[tid + s]);
        __syncthreads();
    }
    float mx = red[0];
    __syncthreads();
    float e0 = expf(v[0] - mx), e1 = expf(v[1] - mx);
    red[tid] = e0 + e1;
    __syncthreads();
    for (int s = 128; s > 0; s >>= 1) {
        if (tid < s) red[tid] += red[tid + s];
        __syncthreads();
    }
    float inv = 1.f / red[0];
    __nv_bfloat16 h, l;
    bf_split(e0 * inv, h, l);
    d_Ah[n * NN + tid] = h; d_Al[n * NN + tid] = l;
    bf_split(e1 * inv, h, l);
    d_Ah[n * NN + tid + 256] = h; d_Al[n * NN + tid + 256] = l;
}

// fused node-adaptive weight + bias materialization (KIP2=160 layout, zero rows)
#define ZR_TOT (NN * KIP2 * 128)
#define C_TOT  (NN * KIP2 * 64)
__global__ void mix_all_kernel(const float* __restrict__ Wzr, const float* __restrict__ Wc,
                               const float* __restrict__ bzr, const float* __restrict__ bc,
                               const float* __restrict__ E1) {
    int idx = blockIdx.x * blockDim.x + threadIdx.x;
    if (idx < ZR_TOT) {
        int o = idx & 127;
        int ki = (idx >> 7) % KIP2;
        int n = idx / (KIP2 * 128);
        float s = 0.f;
        int i = -1;
        if (ki < 66) i = ki;
        else if (ki >= 72 && ki < 138) i = 66 + (ki - 72);
        if (i >= 0) {
            const float* p = Wzr + i * 128 + o;
#pragma unroll
            for (int d = 0; d < DD; d++)
                s = fmaf(E1[n * DD + d], p[d * 2 * 66 * 128], s);
        }
        __nv_bfloat16 h, l;
        bf_split(s, h, l);
        d_Wzrh[idx] = h; d_Wzrl[idx] = l;
    } else if (idx < ZR_TOT + C_TOT) {
        int j = idx - ZR_TOT;
        int o = j & 63;
        int ki = (j >> 6) % KIP2;
        int n = j / (KIP2 * 64);
        float s = 0.f;
        int i = -1;
        if (ki < 66) i = ki;
        else if (ki >= 72 && ki < 138) i = 66 + (ki - 72);
        if (i >= 0) {
            const float* p = Wc + i * 64 + o;
#pragma unroll
            for (int d = 0; d < DD; d++)
                s = fmaf(E1[n * DD + d], p[d * 2 * 66 * 64], s);
        }
        __nv_bfloat16 h, l;
        bf_split(s, h, l);
        d_Wch[j] = h; d_Wcl[j] = l;
    } else if (idx < ZR_TOT + C_TOT + NN * 128) {
        int j = idx - ZR_TOT - C_TOT;
        int n = j >> 7, o = j & 127;
        float s = 0.f;
#pragma unroll
        for (int d = 0; d < DD; d++) s = fmaf(E1[n * DD + d], bzr[d * 128 + o], s);
        d_bnzr[j] = s;
    } else if (idx < ZR_TOT + C_TOT + NN * 128 + NN * 64) {
        int j = idx - ZR_TOT - C_TOT - NN * 128;
        int n = j >> 6, o = j & 63;
        float s = 0.f;
#pragma unroll
        for (int d = 0; d < DD; d++) s = fmaf(E1[n * DD + d], bc[d * 64 + o], s);
        d_bnc[j] = s;
    }
}

// init: uT = [x_0, 0pad], u2T = 0, hT = 0
__global__ void init_kernel(const float* __restrict__ x) {
    int n = blockIdx.y;
    int j = blockIdx.x * 256 + threadIdx.x;
    int b = j / JP, c = j - b * JP;
    float f = (c < CC) ? x[((size_t)(b * TT) * NN + n) * CC + c] : 0.f;
    __nv_bfloat16 h, l;
    bf_split(f, h, l);
    size_t o = (size_t)n * NT + j;
    d_uTh[o] = h; d_uTl[o] = l;
    d_u2Th[o] = __float2bfloat16(0.f);
    d_u2Tl[o] = __float2bfloat16(0.f);
    if (j < BB * HH) d_hT[(size_t)n * BB * HH + j] = 0.f;
}

// ================= GEMM: g[512,4608] = A @ uT (bf16x3), out bf16 hi/lo =================
#define G_AL 5120
#define G_BH 10240
#define G_STAGE 18944

__device__ __forceinline__ void load_stage_g(__nv_bfloat16* s, int m0, int nt0, int k0, int tid,
                                             const __nv_bfloat16* Bh, const __nv_bfloat16* Bl) {
#pragma unroll
    for (int r = 0; r < 2; r++) {     // A: 128 rows x 32 k
        int idx = r * 256 + tid;
        int row = idx >> 2, c = idx & 3;
        uint32_t so = smem_u32(s + row * 40 + c * 8);
        size_t ga = (size_t)(m0 + row) * NN + k0 + c * 8;
        cp16(so, d_Ah + ga);
        cp16(so + G_AL * 2, d_Al + ga);
    }
#pragma unroll
    for (int r = 0; r < 2; r++) {     // B: 32 k-rows x 128 j
        int idx = r * 256 + tid;
        int row = idx >> 4, c = idx & 15;
        uint32_t so = smem_u32(s + G_BH + row * 136 + c * 8);
        size_t gb = (size_t)(k0 + row) * NT + nt0 + c * 8;
        cp16(so, Bh + gb);
        cp16(so + 4352 * 2, Bl + gb);
    }
}

__global__ void __launch_bounds__(256, 1) gemm_tc_kernel(int use_u2) {
    extern __shared__ __nv_bfloat16 dsm[];
    const __nv_bfloat16* Bh = use_u2 ? d_u2Th : d_uTh;
    const __nv_bfloat16* Bl = use_u2 ? d_u2Tl : d_uTl;
    int tid = threadIdx.x;
    int wid = tid >> 5, lane = tid & 31;
    int m0 = blockIdx.x * 128;
    int nt0 = blockIdx.y * 128;
    int wm = (wid & 3) * 32;
    int wn = (wid >> 2) * 64;
    int lrow = lane & 15, lcol = (lane >> 4) * 8;

    float acc[2][8][4];
#pragma unroll
    for (int i = 0; i < 2; i++)
#pragma unroll
        for (int t = 0; t < 8; t++)
#pragma unroll
            for (int r = 0; r < 4; r++) acc[i][t][r] = 0.f;

    load_stage_g(dsm, m0, nt0, 0, tid, Bh, Bl);
    CP_COMMIT();
    load_stage_g(dsm + G_STAGE, m0, nt0, 32, tid, Bh, Bl);
    CP_COMMIT();

    const int NITER = NN / 32;
    for (int it = 0; it < NITER; it++) {
        if (it == NITER - 1) asm volatile("cp.async.wait_group 0;" ::: "memory");
        else                 asm volatile("cp.async.wait_group 1;" ::: "memory");
        __syncthreads();
        __nv_bfloat16* st = dsm + (it & 1) * G_STAGE;

#pragma unroll
        for (int kp = 0; kp < 32; kp += 16) {
            uint32_t ah[2][4], al[2][4], bh[4][4], bl[4][4];
#pragma unroll
            for (int i = 0; i < 2; i++) {
                uint32_t ad = smem_u32(st + (wm + i * 16 + lrow) * 40 + kp + lcol);
                ldsm4(ah[i][0], ah[i][1], ah[i][2], ah[i][3], ad);
                ldsm4(al[i][0], al[i][1], al[i][2], al[i][3], ad + G_AL * 2);
            }
#pragma unroll
            for (int p = 0; p < 4; p++) {
                uint32_t bd = smem_u32(st + G_BH + (kp + lrow) * 136 + wn + p * 16 + lcol);
                ldsm4t(bh[p][0], bh[p][1], bh[p][2], bh[p][3], bd);
                ldsm4t(bl[p][0], bl[p][1], bl[p][2], bl[p][3], bd + 4352 * 2);
            }
#pragma unroll
            for (int i = 0; i < 2; i++) {
#pragma unroll
                for (int t = 0; t < 8; t++) {
                    int p = t >> 1, hf = t & 1;
                    uint32_t b0h = bh[p][hf * 2], b1h = bh[p][hf * 2 + 1];
                    uint32_t b0l = bl[p][hf * 2], b1l = bl[p][hf * 2 + 1];
                    mma_bf16(acc[i][t], ah[i], b0h, b1h);
                    mma_bf16(acc[i][t], ah[i], b0l, b1l);
                    mma_bf16(acc[i][t], al[i], b0h, b1h);
                }
            }
        }
        __syncthreads();
        if (it + 2 < NITER) {
            load_stage_g(dsm + (it & 1) * G_STAGE, m0, nt0, (it + 2) * 32, tid, Bh, Bl);
            CP_COMMIT();
        }
    }

    // epilogue: bf16 hi/lo packed stores
    unsigned short* gh = (unsigned short*)d_gTh;
    unsigned short* gl = (unsigned short*)d_gTl;
#pragma unroll
    for (int i = 0; i < 2; i++) {
        int mr = m0 + wm + i * 16 + (lane >> 2);
#pragma unroll
        for (int t = 0; t < 8; t++) {
            int p = t >> 1, hf = t & 1;
            int col = nt0 + wn + p * 16 + hf * 8 + (lane & 3) * 2;
            uint32_t lo0, lo1;
            uint32_t hi0 = pack_split(acc[i][t][0], acc[i][t][1], lo0);
            uint32_t hi1 = pack_split(acc[i][t][2], acc[i][t][3], lo1);
            *(uint32_t*)(gh + (size_t)mr * NT + col) = hi0;
            *(uint32_t*)(gl + (size_t)mr * NT + col) = lo0;
            *(uint32_t*)(gh + (size_t)(mr + 8) * NT + col) = hi1;
            *(uint32_t*)(gl + (size_t)(mr + 8) * NT + col) = lo1;
        }
    }
}

// ================= gate common: activation staging (pure cp.async) =================
#define SA_STRIDE 168
#define SAL_OFF (64 * SA_STRIDE)     // 10752 elems (lo matrix offset)
#define SW_OFF  (2 * SAL_OFF)        // 21504 elems (weight stages)

__device__ __forceinline__ void stage_acts(__nv_bfloat16* dsm, int n, int tid,
                                           const __nv_bfloat16* Uh, const __nv_bfloat16* Ul) {
#pragma unroll
    for (int j = 0; j < 9; j++) {
        int id = j * 256 + tid;          // 0..2303
        int b = id / 36;
        int q = id - b * 36;
        const __nv_bfloat16* src;
        uint32_t dst;
        if (q < 9) {
            src = Uh + (size_t)n * NT + b * JP + q * 8;
            dst = smem_u32(dsm + b * SA_STRIDE + q * 8);
        } else if (q < 18) {
            src = d_gTh + (size_t)n * NT + b * JP + (q - 9) * 8;
            dst = smem_u32(dsm + b * SA_STRIDE + 72 + (q - 9) * 8);
        } else if (q < 27) {
            src = Ul + (size_t)n * NT + b * JP + (q - 18) * 8;
            dst = smem_u32(dsm + SAL_OFF + b * SA_STRIDE + (q - 18) * 8);
        } else {
            src = d_gTl + (size_t)n * NT + b * JP + (q - 27) * 8;
            dst = smem_u32(dsm + SAL_OFF + b * SA_STRIDE + 72 + (q - 27) * 8);
        }
        cp16(dst, src);
    }
    // zero tail cols 144..159 (hi and lo)
    {
        int mat = tid & 1, ch = (tid >> 1) & 1, row = tid >> 2;
        uint32_t* z = (uint32_t*)(dsm + mat * SAL_OFF + row * SA_STRIDE + 144 + ch * 8);
        z[0] = 0; z[1] = 0; z[2] = 0; z[3] = 0;
    }
}

// ================= gate zr: 64x128xK160 bf16x3 =================
#define ZR_WSTG 4352     // elems per stage (hi 2176 + lo 2176)
#define ZR_WHALF 2176

__device__ __forceinline__ void zr_fill_w(__nv_bfloat16* dsm, int n, int chunk, int stage, int tid) {
#pragma unroll
    for (int j = 0; j < 2; j++) {
        int idx = j * 256 + tid;
        int h = idx >> 8;
        int rem = idx & 255;
        int row = rem >> 4, cc = rem & 15;
        uint32_t so = smem_u32(dsm + SW_OFF + stage * ZR_WSTG + h * ZR_WHALF + row * 136 + cc * 8);
        size_t ga = ((size_t)n * KIP2 + chunk * 16 + row) * 128 + cc * 8;
        cp16(so, (h ? d_Wzrl : d_Wzrh) + ga);
    }
}

__global__ void __launch_bounds__(256, 2) gate_zr_kernel() {
    extern __shared__ __nv_bfloat16 dsm[];
    int n = blockIdx.x;
    int tid = threadIdx.x;
    int wid = tid >> 5, lane = tid & 31;
    int wm16 = (wid & 3) * 16;
    int wn2 = wid >> 2;
    int lrow = lane & 15, lcol = (lane >> 4) * 8;

    if (tid < 64) {   // copy x cols into u2T
        size_t o = (size_t)n * NT + tid * JP;
        d_u2Th[o] = d_uTh[o]; d_u2Th[o + 1] = d_uTh[o + 1];
        d_u2Tl[o] = d_uTl[o]; d_u2Tl[o + 1] = d_uTl[o + 1];
    }

    zr_fill_w(dsm, n, 0, 0, tid);
    stage_acts(dsm, n, tid, d_uTh, d_uTl);
    CP_COMMIT();                        // group: w0 + acts
    zr_fill_w(dsm, n, 1, 1, tid);
    CP_COMMIT();                        // group: w1

    float acc[8][4];
#pragma unroll
    for (int t = 0; t < 8; t++)
#pragma unroll
        for (int r = 0; r < 4; r++) acc[t][r] = 0.f;

    for (int c = 0; c < 10; c++) {
        if (c == 9) asm volatile("cp.async.wait_group 0;" ::: "memory");
        else        asm volatile("cp.async.wait_group 1;" ::: "memory");
        __syncthreads();
        __nv_bfloat16* w = dsm + SW_OFF + (c & 1) * ZR_WSTG;

        uint32_t ah[4], al[4], bh[4][4], bl[4][4];
        uint32_t ad = smem_u32(dsm + (wm16 + lrow) * SA_STRIDE + c * 16 + lcol);
        ldsm4(ah[0], ah[1], ah[2], ah[3], ad);
        ldsm4(al[0], al[1], al[2], al[3], ad + SAL_OFF * 2);
#pragma unroll
        for (int p = 0; p < 4; p++) {
            uint32_t bd = smem_u32(w + lrow * 136 + wn2 * 64 + p * 16 + lcol);
            ldsm4t(bh[p][0], bh[p][1], bh[p][2], bh[p][3], bd);
            ldsm4t(bl[p][0], bl[p][1], bl[p][2], bl[p][3], bd + ZR_WHALF * 2);
        }
#pragma unroll
        for (int t = 0; t < 8; t++) {
            int p = t >> 1, hf = t & 1;
            uint32_t b0h = bh[p][hf * 2], b1h = bh[p][hf * 2 + 1];
            uint32_t b0l = bl[p][hf * 2], b1l = bl[p][hf * 2 + 1];
            mma_bf16(acc[t], ah, b0h, b1h);
            mma_bf16(acc[t], ah, b0l, b1l);
            mma_bf16(acc[t], al, b0h, b1h);
        }
        __syncthreads();
        if (c + 2 < 10) {
            zr_fill_w(dsm, n, c + 2, c & 1, tid);
            CP_COMMIT();
        }
    }

    const float* bias = d_bnzr + n * 128;
#pragma unroll
    for (int t = 0; t < 8; t++) {
        int p = t >> 1, hf = t & 1;
        int oc = wn2 * 64 + p * 16 + hf * 8 + (lane & 3) * 2;
        float bi0 = bias[oc], bi1 = bias[oc + 1];
#pragma unroll
        for (int rr = 0; rr < 2; rr++) {
            int b = wm16 + (lane >> 2) + rr * 8;
            float s0 = 1.f / (1.f + __expf(-(acc[t][rr * 2] + bi0)));
            float s1 = 1.f / (1.f + __expf(-(acc[t][rr * 2 + 1] + bi1)));
            if (wn2 == 0) {
                *(float2*)(d_zT + (size_t)n * BB * HH + b * HH + oc) = make_float2(s0, s1);
            } else {
                int oo = oc - 64;
                size_t hb = (size_t)n * BB * HH + b * HH + oo;
                float r0 = s0 * d_hT[hb];
                float r1 = s1 * d_hT[hb + 1];
                size_t ub = (size_t)n * NT + b * JP + 2 + oo;
                uint32_t lo;
                uint32_t hi = pack_split(r0, r1, lo);
                *(uint32_t*)((unsigned short*)d_u2Th + ub) = hi;
                *(uint32_t*)((unsigned short*)d_u2Tl + ub) = lo;
            }
        }
    }
}

// ================= gate c: 64x64xK160 bf16x3 + GRU update =================
#define C_WSTG 2304
#define C_WHALF 1152

__device__ __forceinline__ void c_fill_w(__nv_bfloat16* dsm, int n, int chunk, int stage, int tid) {
    int h = tid >> 7;
    int rem = tid & 127;
    int row = rem >> 3, cc = rem & 7;
    uint32_t so = smem_u32(dsm + SW_OFF + stage * C_WSTG + h * C_WHALF + row * 72 + cc * 8);
    size_t ga = ((size_t)n * KIP2 + chunk * 16 + row) * 64 + cc * 8;
    cp16(so, (h ? d_Wcl : d_Wch) + ga);
}

__global__ void __launch_bounds__(256, 2) gate_c_kernel(const float* __restrict__ x, int t) {
    extern __shared__ __nv_bfloat16 dsm[];
    int n = blockIdx.x;
    int tid = threadIdx.x;
    int wid = tid >> 5, lane = tid & 31;
    int wm16 = (wid & 3) * 16;
    int wn2 = wid >> 2;
    int lrow = lane & 15, lcol = (lane >> 4) * 8;
    bool more = (t < TT - 1);

    c_fill_w(dsm, n, 0, 0, tid);
    stage_acts(dsm, n, tid, d_u2Th, d_u2Tl);
    CP_COMMIT();
    c_fill_w(dsm, n, 1, 1, tid);
    CP_COMMIT();

    float acc[4][4];
#pragma unroll
    for (int t2 = 0; t2 < 4; t2++)
#pragma unroll
        for (int r = 0; r < 4; r++) acc[t2][r] = 0.f;

    for (int c = 0; c < 10; c++) {
        if (c == 9) asm volatile("cp.async.wait_group 0;" ::: "memory");
        else        asm volatile("cp.async.wait_group 1;" ::: "memory");
        __syncthreads();
        __nv_bfloat16* w = dsm + SW_OFF + (c & 1) * C_WSTG;

        uint32_t ah[4], al[4], bh[2][4], bl[2][4];
        uint32_t ad = smem_u32(dsm + (wm16 + lrow) * SA_STRIDE + c * 16 + lcol);
        ldsm4(ah[0], ah[1], ah[2], ah[3], ad);
        ldsm4(al[0], al[1], al[2], al[3], ad + SAL_OFF * 2);
#pragma unroll
        for (int p = 0; p < 2; p++) {
            uint32_t bd = smem_u32(w + lrow * 72 + wn2 * 32 + p * 16 + lcol);
            ldsm4t(bh[p][0], bh[p][1], bh[p][2], bh[p][3], bd);
            ldsm4t(bl[p][0], bl[p][1], bl[p][2], bl[p][3], bd + C_WHALF * 2);
        }
#pragma unroll
        for (int t2 = 0; t2 < 4; t2++) {
            int p = t2 >> 1, hf = t2 & 1;
            uint32_t b0h = bh[p][hf * 2], b1h = bh[p][hf * 2 + 1];
            uint32_t b0l = bl[p][hf * 2], b1l = bl[p][hf * 2 + 1];
            mma_bf16(acc[t2], ah, b0h, b1h);
            mma_bf16(acc[t2], ah, b0l, b1l);
            mma_bf16(acc[t2], al, b0h, b1h);
        }
        __syncthreads();
        if (c + 2 < 10) {
            c_fill_w(dsm, n, c + 2, c & 1, tid);
            CP_COMMIT();
        }
    }

    const float* bias = d_bnc + n * 64;
#pragma unroll
    for (int t2 = 0; t2 < 4; t2++) {
        int p = t2 >> 1, hf = t2 & 1;
        int oc = wn2 * 32 + p * 16 + hf * 8 + (lane & 3) * 2;
        float bi0 = bias[oc], bi1 = bias[oc + 1];
#pragma unroll
        for (int rr = 0; rr < 2; rr++) {
            int b = wm16 + (lane >> 2) + rr * 8;
            float hc0 = tanhf(acc[t2][rr * 2] + bi0);
            float hc1 = tanhf(acc[t2][rr * 2 + 1] + bi1);
            size_t hb = (size_t)n * BB * HH + b * HH + oc;
            float z0 = d_zT[hb], z1 = d_zT[hb + 1];
            float hn0 = z0 * d_hT[hb] + (1.f - z0) * hc0;
            float hn1 = z1 * d_hT[hb + 1] + (1.f - z1) * hc1;
            d_hT[hb] = hn0;
            d_hT[hb + 1] = hn1;
            if (more) {
                size_t ub = (size_t)n * NT + b * JP + 2 + oc;
                uint32_t lo;
                uint32_t hi = pack_split(hn0, hn1, lo);
                *(uint32_t*)((unsigned short*)d_uTh + ub) = hi;
                *(uint32_t*)((unsigned short*)d_uTl + ub) = lo;
            }
        }
    }
    if (more && tid < 64) {
        int b = tid;
        size_t ub = (size_t)n * NT + b * JP;
#pragma unroll
        for (int c2 = 0; c2 < CC; c2++) {
            float f = x[((size_t)(b * TT + t + 1) * NN + n) * CC + c2];
            __nv_bfloat16 h, l;
            bf_split(f, h, l);
            d_uTh[ub + c2] = h; d_uTl[ub + c2] = l;
        }
    }
}

// ================= readout =================
__global__ void readout_kernel(const float* __restrict__ Wout,
                               const float* __restrict__ bout,
                               float* __restrict__ out) {
    __shared__ float w[HH];
    int n = blockIdx.x;
    int b = threadIdx.x;
    if (b < HH) w[b] = Wout[b];
    __syncthreads();
    const float4* hp = (const float4*)(d_hT + (size_t)n * BB * HH + b * HH);
    float s = bout[0];
#pragma unroll
    for (int q = 0; q < HH / 4; q++) {
        float4 v = hp[q];
        s = fmaf(v.x, w[q * 4 + 0], s);
        s = fmaf(v.y, w[q * 4 + 1], s);
        s = fmaf(v.z, w[q * 4 + 2], s);
        s = fmaf(v.w, w[q * 4 + 3], s);
    }
    out[b * NN + n] = s;
}

// ================= launch =================
extern "C" void kernel_launch(void* const* d_in, const int* in_sizes, int n_in,
                              void* d_out, int out_size) {
    const float* x    = (const float*)d_in[0];
    const float* E1   = (const float*)d_in[1];
    const float* Wzr  = (const float*)d_in[2];
    const float* bzr  = (const float*)d_in[3];
    const float* Wc   = (const float*)d_in[4];
    const float* bc   = (const float*)d_in[5];
    const float* Wout = (const float*)d_in[6];
    const float* bout = (const float*)d_in[7];
    float* out = (float*)d_out;

    const int GEMM_SMEM = 2 * G_STAGE * 2;              // 75776 B
    const int ZR_SMEM = (SW_OFF + 2 * ZR_WSTG) * 2;     // 60416 B
    const int C_SMEM = (SW_OFF + 2 * C_WSTG) * 2;       // 52224 B
    cudaFuncSetAttribute(gemm_tc_kernel, cudaFuncAttributeMaxDynamicSharedMemorySize, GEMM_SMEM);
    cudaFuncSetAttribute(gate_zr_kernel, cudaFuncAttributeMaxDynamicSharedMemorySize, ZR_SMEM);
    cudaFuncSetAttribute(gate_c_kernel, cudaFuncAttributeMaxDynamicSharedMemorySize, C_SMEM);

    compute_A_kernel<<<NN, 256>>>(E1);                                     // launch 1
    {
        int tot = ZR_TOT + C_TOT + NN * 192;
        mix_all_kernel<<<(tot + 255) / 256, 256>>>(Wzr, Wc, bzr, bc, E1);  // launch 2
    }
    {
        dim3 ig(NT / 256, NN);
        init_kernel<<<ig, 256>>>(x);                                       // launch 3
    }

    dim3 ggrid(4, NT / 128);
    for (int t = 0; t < TT; t++) {
        gemm_tc_kernel<<<ggrid, 256, GEMM_SMEM>>>(0);                      // launch 4 at t=0 (profiled)
        gate_zr_kernel<<<NN, 256, ZR_SMEM>>>();
        gemm_tc_kernel<<<ggrid, 256, GEMM_SMEM>>>(1);
        gate_c_kernel<<<NN, 256, C_SMEM>>>(x, t);
    }

    readout_kernel<<<NN, 64>>>(Wout, bout, out);
}

// round 7
// speedup vs baseline: 4.3774x; 1.0137x over previous
#include <cuda_runtime.h>
#include <cuda_bf16.h>
#include <math.h>
#include <stdint.h>

// Problem dims
#define BB 64
#define TT 24
#define NN 512
#define CC 2
#define HH 64
#define DD 16
#define JP 72        // padded per-batch column width
#define NT (BB*JP)   // 4608 GEMM columns (b,c)
#define KIP2 160     // gate K layout: [u:72 | g:72 | pad:16]

// ---------------- device scratch ----------------
__device__ __nv_bfloat16 d_Ah[NN * NN];
__device__ __nv_bfloat16 d_Al[NN * NN];
__device__ __nv_bfloat16 d_uTh[NN * NT];    // [n][(b,c)]
__device__ __nv_bfloat16 d_uTl[NN * NT];
__device__ __nv_bfloat16 d_u2Th[NN * NT];
__device__ __nv_bfloat16 d_u2Tl[NN * NT];
__device__ __nv_bfloat16 d_gTh[NN * NT];    // GEMM output, bf16 hi/lo
__device__ __nv_bfloat16 d_gTl[NN * NT];
__device__ float d_hT[NN * BB * HH];        // [n][(b,o)]
__device__ float d_zT[NN * BB * HH];
__device__ __nv_bfloat16 d_Wzrh[NN * KIP2 * 128];  // [n][ki:160][o]
__device__ __nv_bfloat16 d_Wzrl[NN * KIP2 * 128];
__device__ __nv_bfloat16 d_Wch[NN * KIP2 * 64];
__device__ __nv_bfloat16 d_Wcl[NN * KIP2 * 64];
__device__ float d_bnzr[NN * 128];
__device__ float d_bnc[NN * 64];

// ---------------- helpers ----------------
__device__ __forceinline__ uint32_t smem_u32(const void* p) {
    uint32_t a;
    asm("{ .reg .u64 t; cvta.to.shared.u64 t, %1; cvt.u32.u64 %0, t; }" : "=r"(a) : "l"(p));
    return a;
}
__device__ __forceinline__ void cp16(uint32_t saddr, const void* g) {
    asm volatile("cp.async.cg.shared.global [%0], [%1], 16;" :: "r"(saddr), "l"(g));
}
#define CP_COMMIT() asm volatile("cp.async.commit_group;" ::: "memory")
#define CP_WAIT_PEND(p) do { \
    if ((p) >= 2)      asm volatile("cp.async.wait_group 2;" ::: "memory"); \
    else if ((p) == 1) asm volatile("cp.async.wait_group 1;" ::: "memory"); \
    else               asm volatile("cp.async.wait_group 0;" ::: "memory"); \
} while (0)

__device__ __forceinline__ void ldsm4(uint32_t& r0, uint32_t& r1, uint32_t& r2, uint32_t& r3,
                                      uint32_t addr) {
    asm volatile("ldmatrix.sync.aligned.m8n8.x4.shared.b16 {%0,%1,%2,%3}, [%4];"
                 : "=r"(r0), "=r"(r1), "=r"(r2), "=r"(r3) : "r"(addr));
}
__device__ __forceinline__ void ldsm4t(uint32_t& r0, uint32_t& r1, uint32_t& r2, uint32_t& r3,
                                       uint32_t addr) {
    asm volatile("ldmatrix.sync.aligned.m8n8.x4.trans.shared.b16 {%0,%1,%2,%3}, [%4];"
                 : "=r"(r0), "=r"(r1), "=r"(r2), "=r"(r3) : "r"(addr));
}
__device__ __forceinline__ void mma_bf16(float* c, const uint32_t* a, uint32_t b0, uint32_t b1) {
    asm volatile(
        "mma.sync.aligned.m16n8k16.row.col.f32.bf16.bf16.f32 "
        "{%0,%1,%2,%3}, {%4,%5,%6,%7}, {%8,%9}, {%0,%1,%2,%3};"
        : "+f"(c[0]), "+f"(c[1]), "+f"(c[2]), "+f"(c[3])
        : "r"(a[0]), "r"(a[1]), "r"(a[2]), "r"(a[3]), "r"(b0), "r"(b1));
}
__device__ __forceinline__ void bf_split(float f, __nv_bfloat16& h, __nv_bfloat16& l) {
    h = __float2bfloat16(f);
    l = __float2bfloat16(f - __bfloat162float(h));
}
__device__ __forceinline__ unsigned short bfb(__nv_bfloat16 h) {
    return *reinterpret_cast<unsigned short*>(&h);
}
__device__ __forceinline__ uint32_t pack_split(float a, float b, uint32_t& lo) {
    __nv_bfloat16 h0, l0, h1, l1;
    bf_split(a, h0, l0); bf_split(b, h1, l1);
    lo = (uint32_t)bfb(l0) | ((uint32_t)bfb(l1) << 16);
    return (uint32_t)bfb(h0) | ((uint32_t)bfb(h1) << 16);
}

// ================= setup =================

__global__ void compute_A_kernel(const float* __restrict__ E1) {
    int n = blockIdx.x;
    __shared__ float en[DD];
    __shared__ float red[256];
    int tid = threadIdx.x;
    if (tid < DD) en[tid] = E1[n * DD + tid];
    __syncthreads();
    float v[2];
#pragma unroll
    for (int j = 0; j < 2; j++) {
        const float* em = E1 + (tid + j * 256) * DD;
        float s = 0.f;
#pragma unroll
        for (int d = 0; d < DD; d++) s = fmaf(en[d], em[d], s);
        v[j] = fmaxf(s, 0.f);
    }
    red[tid] = fmaxf(v[0], v[1]);
    __syncthreads();
    for (int s = 128; s > 0; s >>= 1) {
        if (tid < s) red[tid] = fmaxf(red[tid], red[tid + s]);
        __syncthreads();
    }
    float mx = red[0];
    __syncthreads();
    float e0 = expf(v[0] - mx), e1 = expf(v[1] - mx);
    red[tid] = e0 + e1;
    __syncthreads();
    for (int s = 128; s > 0; s >>= 1) {
        if (tid < s) red[tid] += red[tid + s];
        __syncthreads();
    }
    float inv = 1.f / red[0];
    __nv_bfloat16 h, l;
    bf_split(e0 * inv, h, l);
    d_Ah[n * NN + tid] = h; d_Al[n * NN + tid] = l;
    bf_split(e1 * inv, h, l);
    d_Ah[n * NN + tid + 256] = h; d_Al[n * NN + tid + 256] = l;
}

// fused node-adaptive weight + bias materialization (KIP2=160 layout, zero rows)
#define ZR_TOT (NN * KIP2 * 128)
#define C_TOT  (NN * KIP2 * 64)
__global__ void mix_all_kernel(const float* __restrict__ Wzr, const float* __restrict__ Wc,
                               const float* __restrict__ bzr, const float* __restrict__ bc,
                               const float* __restrict__ E1) {
    int idx = blockIdx.x * blockDim.x + threadIdx.x;
    if (idx < ZR_TOT) {
        int o = idx & 127;
        int ki = (idx >> 7) % KIP2;
        int n = idx / (KIP2 * 128);
        float s = 0.f;
        int i = -1;
        if (ki < 66) i = ki;
        else if (ki >= 72 && ki < 138) i = 66 + (ki - 72);
        if (i >= 0) {
            const float* p = Wzr + i * 128 + o;
#pragma unroll
            for (int d = 0; d < DD; d++)
                s = fmaf(E1[n * DD + d], p[d * 2 * 66 * 128], s);
        }
        __nv_bfloat16 h, l;
        bf_split(s, h, l);
        d_Wzrh[idx] = h; d_Wzrl[idx] = l;
    } else if (idx < ZR_TOT + C_TOT) {
        int j = idx - ZR_TOT;
        int o = j & 63;
        int ki = (j >> 6) % KIP2;
        int n = j / (KIP2 * 64);
        float s = 0.f;
        int i = -1;
        if (ki < 66) i = ki;
        else if (ki >= 72 && ki < 138) i = 66 + (ki - 72);
        if (i >= 0) {
            const float* p = Wc + i * 64 + o;
#pragma unroll
            for (int d = 0; d < DD; d++)
                s = fmaf(E1[n * DD + d], p[d * 2 * 66 * 64], s);
        }
        __nv_bfloat16 h, l;
        bf_split(s, h, l);
        d_Wch[j] = h; d_Wcl[j] = l;
    } else if (idx < ZR_TOT + C_TOT + NN * 128) {
        int j = idx - ZR_TOT - C_TOT;
        int n = j >> 7, o = j & 127;
        float s = 0.f;
#pragma unroll
        for (int d = 0; d < DD; d++) s = fmaf(E1[n * DD + d], bzr[d * 128 + o], s);
        d_bnzr[j] = s;
    } else if (idx < ZR_TOT + C_TOT + NN * 128 + NN * 64) {
        int j = idx - ZR_TOT - C_TOT - NN * 128;
        int n = j >> 6, o = j & 63;
        float s = 0.f;
#pragma unroll
        for (int d = 0; d < DD; d++) s = fmaf(E1[n * DD + d], bc[d * 64 + o], s);
        d_bnc[j] = s;
    }
}

// init: uT = [x_0, 0pad], u2T = 0, hT = 0
__global__ void init_kernel(const float* __restrict__ x) {
    int n = blockIdx.y;
    int j = blockIdx.x * 256 + threadIdx.x;
    int b = j / JP, c = j - b * JP;
    float f = (c < CC) ? x[((size_t)(b * TT) * NN + n) * CC + c] : 0.f;
    __nv_bfloat16 h, l;
    bf_split(f, h, l);
    size_t o = (size_t)n * NT + j;
    d_uTh[o] = h; d_uTl[o] = l;
    d_u2Th[o] = __float2bfloat16(0.f);
    d_u2Tl[o] = __float2bfloat16(0.f);
    if (j < BB * HH) d_hT[(size_t)n * BB * HH + j] = 0.f;
}

// ================= GEMM: g[512,4608] = A @ uT (bf16x3), out bf16 hi/lo =================
#define G_AL 5120
#define G_BH 10240
#define G_STAGE 18944

__device__ __forceinline__ void load_stage_g(__nv_bfloat16* s, int m0, int nt0, int k0, int tid,
                                             const __nv_bfloat16* Bh, const __nv_bfloat16* Bl) {
#pragma unroll
    for (int r = 0; r < 2; r++) {     // A: 128 rows x 32 k
        int idx = r * 256 + tid;
        int row = idx >> 2, c = idx & 3;
        uint32_t so = smem_u32(s + row * 40 + c * 8);
        size_t ga = (size_t)(m0 + row) * NN + k0 + c * 8;
        cp16(so, d_Ah + ga);
        cp16(so + G_AL * 2, d_Al + ga);
    }
#pragma unroll
    for (int r = 0; r < 2; r++) {     // B: 32 k-rows x 128 j
        int idx = r * 256 + tid;
        int row = idx >> 4, c = idx & 15;
        uint32_t so = smem_u32(s + G_BH + row * 136 + c * 8);
        size_t gb = (size_t)(k0 + row) * NT + nt0 + c * 8;
        cp16(so, Bh + gb);
        cp16(so + 4352 * 2, Bl + gb);
    }
}

__global__ void __launch_bounds__(256, 1) gemm_tc_kernel(int use_u2) {
    extern __shared__ __nv_bfloat16 dsm[];
    const __nv_bfloat16* Bh = use_u2 ? d_u2Th : d_uTh;
    const __nv_bfloat16* Bl = use_u2 ? d_u2Tl : d_uTl;
    int tid = threadIdx.x;
    int wid = tid >> 5, lane = tid & 31;
    int m0 = blockIdx.x * 128;
    int nt0 = blockIdx.y * 128;
    int wm = (wid & 3) * 32;
    int wn = (wid >> 2) * 64;
    int lrow = lane & 15, lcol = (lane >> 4) * 8;

    float acc[2][8][4];
#pragma unroll
    for (int i = 0; i < 2; i++)
#pragma unroll
        for (int t = 0; t < 8; t++)
#pragma unroll
            for (int r = 0; r < 4; r++) acc[i][t][r] = 0.f;

    // 3-stage pipeline
    load_stage_g(dsm, m0, nt0, 0, tid, Bh, Bl);
    CP_COMMIT();
    load_stage_g(dsm + G_STAGE, m0, nt0, 32, tid, Bh, Bl);
    CP_COMMIT();
    load_stage_g(dsm + 2 * G_STAGE, m0, nt0, 64, tid, Bh, Bl);
    CP_COMMIT();

    const int NITER = NN / 32;   // 16
    for (int it = 0; it < NITER; it++) {
        int pend = NITER - 1 - it;
        CP_WAIT_PEND(pend);
        __syncthreads();
        int sidx = it % 3;
        __nv_bfloat16* st = dsm + sidx * G_STAGE;

#pragma unroll
        for (int kp = 0; kp < 32; kp += 16) {
            uint32_t ah[2][4], al[2][4], bh[4][4], bl[4][4];
#pragma unroll
            for (int i = 0; i < 2; i++) {
                uint32_t ad = smem_u32(st + (wm + i * 16 + lrow) * 40 + kp + lcol);
                ldsm4(ah[i][0], ah[i][1], ah[i][2], ah[i][3], ad);
                ldsm4(al[i][0], al[i][1], al[i][2], al[i][3], ad + G_AL * 2);
            }
#pragma unroll
            for (int p = 0; p < 4; p++) {
                uint32_t bd = smem_u32(st + G_BH + (kp + lrow) * 136 + wn + p * 16 + lcol);
                ldsm4t(bh[p][0], bh[p][1], bh[p][2], bh[p][3], bd);
                ldsm4t(bl[p][0], bl[p][1], bl[p][2], bl[p][3], bd + 4352 * 2);
            }
            // pass-split ordering: 16 independent accs between reuses
#pragma unroll
            for (int i = 0; i < 2; i++)
#pragma unroll
                for (int t = 0; t < 8; t++) {
                    int p = t >> 1, hf = t & 1;
                    mma_bf16(acc[i][t], ah[i], bh[p][hf * 2], bh[p][hf * 2 + 1]);
                }
#pragma unroll
            for (int i = 0; i < 2; i++)
#pragma unroll
                for (int t = 0; t < 8; t++) {
                    int p = t >> 1, hf = t & 1;
                    mma_bf16(acc[i][t], ah[i], bl[p][hf * 2], bl[p][hf * 2 + 1]);
                }
#pragma unroll
            for (int i = 0; i < 2; i++)
#pragma unroll
                for (int t = 0; t < 8; t++) {
                    int p = t >> 1, hf = t & 1;
                    mma_bf16(acc[i][t], al[i], bh[p][hf * 2], bh[p][hf * 2 + 1]);
                }
        }
        __syncthreads();
        if (it + 3 < NITER) {
            load_stage_g(dsm + sidx * G_STAGE, m0, nt0, (it + 3) * 32, tid, Bh, Bl);
            CP_COMMIT();
        }
    }

    // epilogue: bf16 hi/lo packed stores
    unsigned short* gh = (unsigned short*)d_gTh;
    unsigned short* gl = (unsigned short*)d_gTl;
#pragma unroll
    for (int i = 0; i < 2; i++) {
        int mr = m0 + wm + i * 16 + (lane >> 2);
#pragma unroll
        for (int t = 0; t < 8; t++) {
            int p = t >> 1, hf = t & 1;
            int col = nt0 + wn + p * 16 + hf * 8 + (lane & 3) * 2;
            uint32_t lo0, lo1;
            uint32_t hi0 = pack_split(acc[i][t][0], acc[i][t][1], lo0);
            uint32_t hi1 = pack_split(acc[i][t][2], acc[i][t][3], lo1);
            *(uint32_t*)(gh + (size_t)mr * NT + col) = hi0;
            *(uint32_t*)(gl + (size_t)mr * NT + col) = lo0;
            *(uint32_t*)(gh + (size_t)(mr + 8) * NT + col) = hi1;
            *(uint32_t*)(gl + (size_t)(mr + 8) * NT + col) = lo1;
        }
    }
}

// ================= gate common: activation staging (pure cp.async) =================
#define SA_STRIDE 168
#define SAL_OFF (64 * SA_STRIDE)     // 10752 elems (lo matrix offset)
#define SW_OFF  (2 * SAL_OFF)        // 21504 elems (weight stages)

__device__ __forceinline__ void stage_acts(__nv_bfloat16* dsm, int n, int tid,
                                           const __nv_bfloat16* Uh, const __nv_bfloat16* Ul) {
#pragma unroll
    for (int j = 0; j < 9; j++) {
        int id = j * 256 + tid;          // 0..2303
        int b = id / 36;
        int q = id - b * 36;
        const __nv_bfloat16* src;
        uint32_t dst;
        if (q < 9) {
            src = Uh + (size_t)n * NT + b * JP + q * 8;
            dst = smem_u32(dsm + b * SA_STRIDE + q * 8);
        } else if (q < 18) {
            src = d_gTh + (size_t)n * NT + b * JP + (q - 9) * 8;
            dst = smem_u32(dsm + b * SA_STRIDE + 72 + (q - 9) * 8);
        } else if (q < 27) {
            src = Ul + (size_t)n * NT + b * JP + (q - 18) * 8;
            dst = smem_u32(dsm + SAL_OFF + b * SA_STRIDE + (q - 18) * 8);
        } else {
            src = d_gTl + (size_t)n * NT + b * JP + (q - 27) * 8;
            dst = smem_u32(dsm + SAL_OFF + b * SA_STRIDE + 72 + (q - 27) * 8);
        }
        cp16(dst, src);
    }
    // zero tail cols 144..159 (hi and lo)
    {
        int mat = tid & 1, ch = (tid >> 1) & 1, row = tid >> 2;
        uint32_t* z = (uint32_t*)(dsm + mat * SAL_OFF + row * SA_STRIDE + 144 + ch * 8);
        z[0] = 0; z[1] = 0; z[2] = 0; z[3] = 0;
    }
}

// ================= gate zr: 64x128xK160 bf16x3 =================
#define ZR_WSTG 4352     // elems per stage (hi 2176 + lo 2176)
#define ZR_WHALF 2176

__device__ __forceinline__ void zr_fill_w(__nv_bfloat16* dsm, int n, int chunk, int stage, int tid) {
#pragma unroll
    for (int j = 0; j < 2; j++) {
        int idx = j * 256 + tid;
        int h = idx >> 8;
        int rem = idx & 255;
        int row = rem >> 4, cc = rem & 15;
        uint32_t so = smem_u32(dsm + SW_OFF + stage * ZR_WSTG + h * ZR_WHALF + row * 136 + cc * 8);
        size_t ga = ((size_t)n * KIP2 + chunk * 16 + row) * 128 + cc * 8;
        cp16(so, (h ? d_Wzrl : d_Wzrh) + ga);
    }
}

__global__ void __launch_bounds__(256, 2) gate_zr_kernel() {
    extern __shared__ __nv_bfloat16 dsm[];
    int n = blockIdx.x;
    int tid = threadIdx.x;
    int wid = tid >> 5, lane = tid & 31;
    int wm16 = (wid & 3) * 16;
    int wn2 = wid >> 2;
    int lrow = lane & 15, lcol = (lane >> 4) * 8;

    if (tid < 64) {   // copy x cols into u2T
        size_t o = (size_t)n * NT + tid * JP;
        d_u2Th[o] = d_uTh[o]; d_u2Th[o + 1] = d_uTh[o + 1];
        d_u2Tl[o] = d_uTl[o]; d_u2Tl[o + 1] = d_uTl[o + 1];
    }

    zr_fill_w(dsm, n, 0, 0, tid);
    stage_acts(dsm, n, tid, d_uTh, d_uTl);
    CP_COMMIT();                        // group: w0 + acts
    zr_fill_w(dsm, n, 1, 1, tid);
    CP_COMMIT();                        // group: w1
    zr_fill_w(dsm, n, 2, 2, tid);
    CP_COMMIT();                        // group: w2

    float acc[8][4];
#pragma unroll
    for (int t = 0; t < 8; t++)
#pragma unroll
        for (int r = 0; r < 4; r++) acc[t][r] = 0.f;

    const int NCH = 10;
    for (int c = 0; c < NCH; c++) {
        int pend = NCH - 1 - c;
        CP_WAIT_PEND(pend);
        __syncthreads();
        __nv_bfloat16* w = dsm + SW_OFF + (c % 3) * ZR_WSTG;

        uint32_t ah[4], al[4], bh[4][4], bl[4][4];
        uint32_t ad = smem_u32(dsm + (wm16 + lrow) * SA_STRIDE + c * 16 + lcol);
        ldsm4(ah[0], ah[1], ah[2], ah[3], ad);
        ldsm4(al[0], al[1], al[2], al[3], ad + SAL_OFF * 2);
#pragma unroll
        for (int p = 0; p < 4; p++) {
            uint32_t bd = smem_u32(w + lrow * 136 + wn2 * 64 + p * 16 + lcol);
            ldsm4t(bh[p][0], bh[p][1], bh[p][2], bh[p][3], bd);
            ldsm4t(bl[p][0], bl[p][1], bl[p][2], bl[p][3], bd + ZR_WHALF * 2);
        }
        // pass-split: 8 accs between reuses
#pragma unroll
        for (int t = 0; t < 8; t++) {
            int p = t >> 1, hf = t & 1;
            mma_bf16(acc[t], ah, bh[p][hf * 2], bh[p][hf * 2 + 1]);
        }
#pragma unroll
        for (int t = 0; t < 8; t++) {
            int p = t >> 1, hf = t & 1;
            mma_bf16(acc[t], ah, bl[p][hf * 2], bl[p][hf * 2 + 1]);
        }
#pragma unroll
        for (int t = 0; t < 8; t++) {
            int p = t >> 1, hf = t & 1;
            mma_bf16(acc[t], al, bh[p][hf * 2], bh[p][hf * 2 + 1]);
        }
        __syncthreads();
        if (c + 3 < NCH) {
            zr_fill_w(dsm, n, c + 3, c % 3, tid);
            CP_COMMIT();
        }
    }

    const float* bias = d_bnzr + n * 128;
#pragma unroll
    for (int t = 0; t < 8; t++) {
        int p = t >> 1, hf = t & 1;
        int oc = wn2 * 64 + p * 16 + hf * 8 + (lane & 3) * 2;
        float bi0 = bias[oc], bi1 = bias[oc + 1];
#pragma unroll
        for (int rr = 0; rr < 2; rr++) {
            int b = wm16 + (lane >> 2) + rr * 8;
            float s0 = 1.f / (1.f + __expf(-(acc[t][rr * 2] + bi0)));
            float s1 = 1.f / (1.f + __expf(-(acc[t][rr * 2 + 1] + bi1)));
            if (wn2 == 0) {
                *(float2*)(d_zT + (size_t)n * BB * HH + b * HH + oc) = make_float2(s0, s1);
            } else {
                int oo = oc - 64;
                size_t hb = (size_t)n * BB * HH + b * HH + oo;
                float r0 = s0 * d_hT[hb];
                float r1 = s1 * d_hT[hb + 1];
                size_t ub = (size_t)n * NT + b * JP + 2 + oo;
                uint32_t lo;
                uint32_t hi = pack_split(r0, r1, lo);
                *(uint32_t*)((unsigned short*)d_u2Th + ub) = hi;
                *(uint32_t*)((unsigned short*)d_u2Tl + ub) = lo;
            }
        }
    }
}

// ================= gate c: 64x64xK160 bf16x3 + GRU update =================
#define C_WSTG 2304
#define C_WHALF 1152

__device__ __forceinline__ void c_fill_w(__nv_bfloat16* dsm, int n, int chunk, int stage, int tid) {
    int h = tid >> 7;
    int rem = tid & 127;
    int row = rem >> 3, cc = rem & 7;
    uint32_t so = smem_u32(dsm + SW_OFF + stage * C_WSTG + h * C_WHALF + row * 72 + cc * 8);
    size_t ga = ((size_t)n * KIP2 + chunk * 16 + row) * 64 + cc * 8;
    cp16(so, (h ? d_Wcl : d_Wch) + ga);
}

__global__ void __launch_bounds__(256, 2) gate_c_kernel(const float* __restrict__ x, int t) {
    extern __shared__ __nv_bfloat16 dsm[];
    int n = blockIdx.x;
    int tid = threadIdx.x;
    int wid = tid >> 5, lane = tid & 31;
    int wm16 = (wid & 3) * 16;
    int wn2 = wid >> 2;
    int lrow = lane & 15, lcol = (lane >> 4) * 8;
    bool more = (t < TT - 1);

    c_fill_w(dsm, n, 0, 0, tid);
    stage_acts(dsm, n, tid, d_u2Th, d_u2Tl);
    CP_COMMIT();
    c_fill_w(dsm, n, 1, 1, tid);
    CP_COMMIT();
    c_fill_w(dsm, n, 2, 2, tid);
    CP_COMMIT();

    float acc[4][4];
#pragma unroll
    for (int t2 = 0; t2 < 4; t2++)
#pragma unroll
        for (int r = 0; r < 4; r++) acc[t2][r] = 0.f;

    const int NCH = 10;
    for (int c = 0; c < NCH; c++) {
        int pend = NCH - 1 - c;
        CP_WAIT_PEND(pend);
        __syncthreads();
        __nv_bfloat16* w = dsm + SW_OFF + (c % 3) * C_WSTG;

        uint32_t ah[4], al[4], bh[2][4], bl[2][4];
        uint32_t ad = smem_u32(dsm + (wm16 + lrow) * SA_STRIDE + c * 16 + lcol);
        ldsm4(ah[0], ah[1], ah[2], ah[3], ad);
        ldsm4(al[0], al[1], al[2], al[3], ad + SAL_OFF * 2);
#pragma unroll
        for (int p = 0; p < 2; p++) {
            uint32_t bd = smem_u32(w + lrow * 72 + wn2 * 32 + p * 16 + lcol);
            ldsm4t(bh[p][0], bh[p][1], bh[p][2], bh[p][3], bd);
            ldsm4t(bl[p][0], bl[p][1], bl[p][2], bl[p][3], bd + C_WHALF * 2);
        }
        // pass-split: 4 accs between reuses
#pragma unroll
        for (int t2 = 0; t2 < 4; t2++) {
            int p = t2 >> 1, hf = t2 & 1;
            mma_bf16(acc[t2], ah, bh[p][hf * 2], bh[p][hf * 2 + 1]);
        }
#pragma unroll
        for (int t2 = 0; t2 < 4; t2++) {
            int p = t2 >> 1, hf = t2 & 1;
            mma_bf16(acc[t2], ah, bl[p][hf * 2], bl[p][hf * 2 + 1]);
        }
#pragma unroll
        for (int t2 = 0; t2 < 4; t2++) {
            int p = t2 >> 1, hf = t2 & 1;
            mma_bf16(acc[t2], al, bh[p][hf * 2], bh[p][hf * 2 + 1]);
        }
        __syncthreads();
        if (c + 3 < NCH) {
            c_fill_w(dsm, n, c + 3, c % 3, tid);
            CP_COMMIT();
        }
    }

    const float* bias = d_bnc + n * 64;
#pragma unroll
    for (int t2 = 0; t2 < 4; t2++) {
        int p = t2 >> 1, hf = t2 & 1;
        int oc = wn2 * 32 + p * 16 + hf * 8 + (lane & 3) * 2;
        float bi0 = bias[oc], bi1 = bias[oc + 1];
#pragma unroll
        for (int rr = 0; rr < 2; rr++) {
            int b = wm16 + (lane >> 2) + rr * 8;
            float hc0 = tanhf(acc[t2][rr * 2] + bi0);
            float hc1 = tanhf(acc[t2][rr * 2 + 1] + bi1);
            size_t hb = (size_t)n * BB * HH + b * HH + oc;
            float z0 = d_zT[hb], z1 = d_zT[hb + 1];
            float hn0 = z0 * d_hT[hb] + (1.f - z0) * hc0;
            float hn1 = z1 * d_hT[hb + 1] + (1.f - z1) * hc1;
            d_hT[hb] = hn0;
            d_hT[hb + 1] = hn1;
            if (more) {
                size_t ub = (size_t)n * NT + b * JP + 2 + oc;
                uint32_t lo;
                uint32_t hi = pack_split(hn0, hn1, lo);
                *(uint32_t*)((unsigned short*)d_uTh + ub) = hi;
                *(uint32_t*)((unsigned short*)d_uTl + ub) = lo;
            }
        }
    }
    if (more && tid < 64) {
        int b = tid;
        size_t ub = (size_t)n * NT + b * JP;
#pragma unroll
        for (int c2 = 0; c2 < CC; c2++) {
            float f = x[((size_t)(b * TT + t + 1) * NN + n) * CC + c2];
            __nv_bfloat16 h, l;
            bf_split(f, h, l);
            d_uTh[ub + c2] = h; d_uTl[ub + c2] = l;
        }
    }
}

// ================= readout =================
__global__ void readout_kernel(const float* __restrict__ Wout,
                               const float* __restrict__ bout,
                               float* __restrict__ out) {
    __shared__ float w[HH];
    int n = blockIdx.x;
    int b = threadIdx.x;
    if (b < HH) w[b] = Wout[b];
    __syncthreads();
    const float4* hp = (const float4*)(d_hT + (size_t)n * BB * HH + b * HH);
    float s = bout[0];
#pragma unroll
    for (int q = 0; q < HH / 4; q++) {
        float4 v = hp[q];
        s = fmaf(v.x, w[q * 4 + 0], s);
        s = fmaf(v.y, w[q * 4 + 1], s);
        s = fmaf(v.z, w[q * 4 + 2], s);
        s = fmaf(v.w, w[q * 4 + 3], s);
    }
    out[b * NN + n] = s;
}

// ================= launch =================
extern "C" void kernel_launch(void* const* d_in, const int* in_sizes, int n_in,
                              void* d_out, int out_size) {
    const float* x    = (const float*)d_in[0];
    const float* E1   = (const float*)d_in[1];
    const float* Wzr  = (const float*)d_in[2];
    const float* bzr  = (const float*)d_in[3];
    const float* Wc   = (const float*)d_in[4];
    const float* bc   = (const float*)d_in[5];
    const float* Wout = (const float*)d_in[6];
    const float* bout = (const float*)d_in[7];
    float* out = (float*)d_out;

    const int GEMM_SMEM = 3 * G_STAGE * 2;              // 113664 B
    const int ZR_SMEM = (SW_OFF + 3 * ZR_WSTG) * 2;     // 69120 B
    const int C_SMEM = (SW_OFF + 3 * C_WSTG) * 2;       // 56832 B
    cudaFuncSetAttribute(gemm_tc_kernel, cudaFuncAttributeMaxDynamicSharedMemorySize, GEMM_SMEM);
    cudaFuncSetAttribute(gate_zr_kernel, cudaFuncAttributeMaxDynamicSharedMemorySize, ZR_SMEM);
    cudaFuncSetAttribute(gate_c_kernel, cudaFuncAttributeMaxDynamicSharedMemorySize, C_SMEM);

    compute_A_kernel<<<NN, 256>>>(E1);                                     // launch 1
    {
        int tot = ZR_TOT + C_TOT + NN * 192;
        mix_all_kernel<<<(tot + 255) / 256, 256>>>(Wzr, Wc, bzr, bc, E1);  // launch 2
    }
    {
        dim3 ig(NT / 256, NN);
        init_kernel<<<ig, 256>>>(x);                                       // launch 3
    }

    dim3 ggrid(4, NT / 128);
    for (int t = 0; t < TT; t++) {
        gemm_tc_kernel<<<ggrid, 256, GEMM_SMEM>>>(0);                      // launch 4 at t=0 (profiled)
        gate_zr_kernel<<<NN, 256, ZR_SMEM>>>();
        gemm_tc_kernel<<<ggrid, 256, GEMM_SMEM>>>(1);
        gate_c_kernel<<<NN, 256, C_SMEM>>>(x, t);
    }

    readout_kernel<<<NN, 64>>>(Wout, bout, out);
}